// round 9
// baseline (speedup 1.0000x reference)
#include <cuda_runtime.h>
#include <cuda_bf16.h>
#include <cstdint>

#define DIMSZ 768
#define NTOK 1024
#define BATCH 8
#define HEADS 12
#define DH 64
#define NROWS (BATCH * NTOK)      /* 8192 */
#define QKVN (3 * DIMSZ)          /* 2304 */
#define SCALE 0.125f              /* DH^-0.5 */

typedef unsigned short u16;
typedef uint32_t u32;

// ---------------- scratch (device globals, allocation-free) ----------------
__device__ u16 g_xnh[NROWS * DIMSZ];
__device__ u16 g_xnl[NROWS * DIMSZ];
__device__ u16 g_wqh[QKVN * DIMSZ];      // Wqkv^T hi  [2304][768]
__device__ u16 g_wql[QKVN * DIMSZ];
__device__ u16 g_woh[DIMSZ * DIMSZ];     // Wout^T hi  [768][768]
__device__ u16 g_wol[DIMSZ * DIMSZ];
__device__ u16 g_qkvh[NROWS * QKVN];
__device__ u16 g_qkvl[NROWS * QKVN];
__device__ u16 g_vth[BATCH * HEADS * DH * NTOK];   // V^T [b][h][d][j]
__device__ u16 g_vtl[BATCH * HEADS * DH * NTOK];
__device__ u16 g_atth[NROWS * DIMSZ];
__device__ u16 g_attl[NROWS * DIMSZ];

// ---------------- helpers ----------------
__device__ __forceinline__ u32 smem_u32(const void* p) {
    u32 a;
    asm("{ .reg .u64 t; cvta.to.shared.u64 t, %1; cvt.u32.u64 %0, t; }" : "=r"(a) : "l"(p));
    return a;
}
__device__ __forceinline__ void ldsm_x4(u32 addr, u32* r) {
    asm volatile("ldmatrix.sync.aligned.m8n8.x4.shared.b16 {%0,%1,%2,%3}, [%4];"
                 : "=r"(r[0]), "=r"(r[1]), "=r"(r[2]), "=r"(r[3]) : "r"(addr));
}
__device__ __forceinline__ void mma16816(float* c, const u32* a, u32 b0, u32 b1) {
    asm volatile("mma.sync.aligned.m16n8k16.row.col.f32.bf16.bf16.f32 "
                 "{%0,%1,%2,%3}, {%4,%5,%6,%7}, {%8,%9}, {%0,%1,%2,%3};"
                 : "+f"(c[0]), "+f"(c[1]), "+f"(c[2]), "+f"(c[3])
                 : "r"(a[0]), "r"(a[1]), "r"(a[2]), "r"(a[3]), "r"(b0), "r"(b1));
}
#define CP16(dst, src) \
    asm volatile("cp.async.cg.shared.global [%0], [%1], 16;" :: "r"(dst), "l"(src))
#define CP_COMMIT() asm volatile("cp.async.commit_group;" ::: "memory")
#define CP_WAIT0()  asm volatile("cp.async.wait_group 0;" ::: "memory")
#define CP_WAIT1()  asm volatile("cp.async.wait_group 1;" ::: "memory")

__device__ __forceinline__ void split_bf16(float x, u16& h, u16& l) {
    __nv_bfloat16 hb = __float2bfloat16_rn(x);
    float hf = __bfloat162float(hb);
    __nv_bfloat16 lb = __float2bfloat16_rn(x - hf);
    h = __bfloat16_as_ushort(hb);
    l = __bfloat16_as_ushort(lb);
}
__device__ __forceinline__ void split2(float a, float b, u32& hp, u32& lp) {
    u16 ha, la, hb, lb;
    split_bf16(a, ha, la);
    split_bf16(b, hb, lb);
    hp = (u32)ha | ((u32)hb << 16);
    lp = (u32)la | ((u32)lb << 16);
}

// ===========================================================================
// LayerNorm -> split bf16 hi/lo
// ===========================================================================
__global__ __launch_bounds__(256) void ln_kernel(const float* __restrict__ x,
                                                 const float* __restrict__ gamma,
                                                 const float* __restrict__ beta,
                                                 u16* __restrict__ yh,
                                                 u16* __restrict__ yl) {
    int row = blockIdx.x;
    int t = threadIdx.x;
    __shared__ float sv[DIMSZ];
    __shared__ float sb[8], ssb[8];
    __shared__ float smu, srstd;
    const float* xr = x + (size_t)row * DIMSZ;
    float v0 = xr[t], v1 = xr[t + 256], v2 = xr[t + 512];
    float s = v0 + v1 + v2;
    float ss = v0 * v0 + v1 * v1 + v2 * v2;
#pragma unroll
    for (int o = 16; o > 0; o >>= 1) {
        s += __shfl_xor_sync(0xffffffffu, s, o);
        ss += __shfl_xor_sync(0xffffffffu, ss, o);
    }
    if ((t & 31) == 0) { sb[t >> 5] = s; ssb[t >> 5] = ss; }
    __syncthreads();
    if (t == 0) {
        float S = 0.f, SS = 0.f;
#pragma unroll
        for (int i = 0; i < 8; i++) { S += sb[i]; SS += ssb[i]; }
        float mu = S * (1.0f / DIMSZ);
        float var = SS * (1.0f / DIMSZ) - mu * mu;
        smu = mu;
        srstd = rsqrtf(var + 1e-5f);
    }
    __syncthreads();
    float mu = smu, rstd = srstd;
    sv[t]       = (v0 - mu) * rstd * gamma[t]       + beta[t];
    sv[t + 256] = (v1 - mu) * rstd * gamma[t + 256] + beta[t + 256];
    sv[t + 512] = (v2 - mu) * rstd * gamma[t + 512] + beta[t + 512];
    __syncthreads();
    u32* oh = (u32*)(yh + (size_t)row * DIMSZ);
    u32* ol = (u32*)(yl + (size_t)row * DIMSZ);
    for (int p = t; p < DIMSZ / 2; p += 256) {
        u32 hp, lp;
        split2(sv[2 * p], sv[2 * p + 1], hp, lp);
        oh[p] = hp;
        ol[p] = lp;
    }
}

// ===========================================================================
// Weight transpose + split: W[768][N] -> Wt hi/lo [N][768]
// ===========================================================================
__global__ __launch_bounds__(256) void wprep_kernel(const float* __restrict__ W,
                                                    u16* __restrict__ Wth,
                                                    u16* __restrict__ Wtl,
                                                    int Nsz) {
    __shared__ float sm[32][33];
    int tx = threadIdx.x & 31, ty = threadIdx.x >> 5;   // 32 x 8
    int n0 = blockIdx.x * 32, k0 = blockIdx.y * 32;
#pragma unroll
    for (int i = 0; i < 4; i++)
        sm[ty + i * 8][tx] = W[(size_t)(k0 + ty + i * 8) * Nsz + n0 + tx];
    __syncthreads();
#pragma unroll
    for (int i = 0; i < 4; i++) {
        int n = n0 + ty + i * 8, k = k0 + tx;
        u16 h, l;
        split_bf16(sm[tx][ty + i * 8], h, l);
        Wth[(size_t)n * DIMSZ + k] = h;
        Wtl[(size_t)n * DIMSZ + k] = l;
    }
}

// ===========================================================================
// V transpose: qkv (V part) [b][j][h*64+d] -> vt [b][h][d][j]
// ===========================================================================
__global__ __launch_bounds__(256) void vtrans_kernel(const u16* __restrict__ qh,
                                                     const u16* __restrict__ ql,
                                                     u16* __restrict__ vh,
                                                     u16* __restrict__ vl) {
    __shared__ u16 sm[64][66];
    int t = threadIdx.x;
    int j0 = blockIdx.x * 64, h = blockIdx.y, b = blockIdx.z;
    const u16* srcs[2] = {qh, ql};
    u16* dsts[2] = {vh, vl};
#pragma unroll
    for (int pass = 0; pass < 2; pass++) {
        const u16* src = srcs[pass];
        u16* dst = dsts[pass];
#pragma unroll
        for (int i = 0; i < 8; i++) {
            int id = t + i * 256;          // 0..2047
            int jj = id >> 5, dp = id & 31;
            u32 v = *(const u32*)(src + (size_t)(b * NTOK + j0 + jj) * QKVN +
                                  2 * DIMSZ + h * DH + dp * 2);
            sm[jj][2 * dp] = (u16)v;
            sm[jj][2 * dp + 1] = (u16)(v >> 16);
        }
        __syncthreads();
#pragma unroll
        for (int i = 0; i < 8; i++) {
            int id = t + i * 256;
            int d = id >> 5, jp = id & 31;
            u32 v = (u32)sm[2 * jp][d] | ((u32)sm[2 * jp + 1][d] << 16);
            *(u32*)(dst + ((size_t)((b * HEADS + h) * DH + d)) * NTOK + j0 + 2 * jp) = v;
        }
        __syncthreads();
    }
}

// ===========================================================================
// Split-bf16 GEMM: CTA 256x128, 512 thr (16 warps), warp tile 64x32,
// KC=64, NBUF=2 cp.async stages.  48-MMA runs per ks-step per warp.
// EPI 0: fp32 out + bias.  EPI 1: split bf16 out (hi/lo), SCALE on n<768.
// ===========================================================================
#define TROW 144                   /* 64 bf16 (128B) + 16B pad */
#define ATILE_G (256 * TROW)       /* 36864: one A half (hi or lo) */
#define BTILE_G (128 * TROW)       /* 18432: one B half */
#define STAGE (2 * ATILE_G + 2 * BTILE_G)  /* 110592 */
#define NBUF 2
#define GEMM_SMEM (NBUF * STAGE)   /* 221184 */
#define KC 64
#define NSTAGE (DIMSZ / KC)        /* 12 */
#define B_OFF (2 * ATILE_G)        /* 73728 */

template <int EPI>
__global__ __launch_bounds__(512, 1) void mma_gemm(const u16* __restrict__ Ah,
                                                   const u16* __restrict__ Al,
                                                   const u16* __restrict__ Bh,
                                                   const u16* __restrict__ Bl,
                                                   const float* __restrict__ bias,
                                                   float* __restrict__ Cf,
                                                   u16* __restrict__ Ch,
                                                   u16* __restrict__ Cl,
                                                   int Nsz) {
    extern __shared__ char smem[];
    const u32 smb = smem_u32(smem);
    const int t = threadIdx.x;
    const int wid = t >> 5, lane = t & 31;
    const int m0 = blockIdx.y * 256, n0 = blockIdx.x * 128;
    const int wm = (wid >> 2) * 64, wn = (wid & 3) * 32;   // 4x4 grid, 64x32 tiles

    float acc[4][4][4];
#pragma unroll
    for (int i = 0; i < 4; i++)
#pragma unroll
        for (int j = 0; j < 4; j++)
#pragma unroll
            for (int k = 0; k < 4; k++) acc[i][j][k] = 0.f;

    const int arow = t >> 1, ahalf = t & 1;   // A fill: 256 rows, 64B halves
    const int brw = t >> 2, bq = t & 3;       // B fill: 128 rows, 32B quarters

    auto fill = [&](int c) {
        const u32 base = smb + (c & 1) * STAGE;
        const size_t aoff = (size_t)(m0 + arow) * DIMSZ + c * KC + ahalf * 32;
        const u32 adoff = (u32)(arow * TROW + ahalf * 64);
#pragma unroll
        for (int i = 0; i < 4; i++) {
            CP16(base + adoff + i * 16, Ah + aoff + i * 8);
            CP16(base + ATILE_G + adoff + i * 16, Al + aoff + i * 8);
        }
        const size_t boff = (size_t)(n0 + brw) * DIMSZ + c * KC + bq * 16;
        const u32 bdoff = (u32)(brw * TROW + bq * 32);
        CP16(base + B_OFF + bdoff, Bh + boff);
        CP16(base + B_OFF + bdoff + 16, Bh + boff + 8);
        CP16(base + B_OFF + BTILE_G + bdoff, Bl + boff);
        CP16(base + B_OFF + BTILE_G + bdoff + 16, Bl + boff + 8);
    };

    const int brow = ((lane >> 4) << 3) + (lane & 7);

    auto compute = [&](int c) {
        const u32 base = smb + (c & 1) * STAGE;
#pragma unroll
        for (int ks = 0; ks < 4; ks++) {
            u32 Ahf[4][4], Alf[4][4], Bhf[2][4], Blf[2][4];
            const u32 akb = (u32)(ks * 32 + ((lane & 16) ? 16 : 0));
#pragma unroll
            for (int mt = 0; mt < 4; mt++) {
                u32 ra = base + (u32)((wm + mt * 16 + (lane & 15)) * TROW) + akb;
                ldsm_x4(ra, Ahf[mt]);
                ldsm_x4(ra + ATILE_G, Alf[mt]);
            }
            const u32 bkb = (u32)(ks * 32 + ((lane & 8) ? 16 : 0));
#pragma unroll
            for (int bt = 0; bt < 2; bt++) {
                u32 rb = base + B_OFF + (u32)((wn + bt * 16 + brow) * TROW) + bkb;
                ldsm_x4(rb, Bhf[bt]);
                ldsm_x4(rb + BTILE_G, Blf[bt]);
            }
#pragma unroll
            for (int mt = 0; mt < 4; mt++)
#pragma unroll
                for (int nt = 0; nt < 4; nt++)
                    mma16816(acc[mt][nt], Ahf[mt],
                             Bhf[nt >> 1][(nt & 1) * 2], Bhf[nt >> 1][(nt & 1) * 2 + 1]);
#pragma unroll
            for (int mt = 0; mt < 4; mt++)
#pragma unroll
                for (int nt = 0; nt < 4; nt++)
                    mma16816(acc[mt][nt], Ahf[mt],
                             Blf[nt >> 1][(nt & 1) * 2], Blf[nt >> 1][(nt & 1) * 2 + 1]);
#pragma unroll
            for (int mt = 0; mt < 4; mt++)
#pragma unroll
                for (int nt = 0; nt < 4; nt++)
                    mma16816(acc[mt][nt], Alf[mt],
                             Bhf[nt >> 1][(nt & 1) * 2], Bhf[nt >> 1][(nt & 1) * 2 + 1]);
        }
    };

    // 2-stage pipeline, always-commit
    fill(0); CP_COMMIT();
    fill(1); CP_COMMIT();
    for (int c = 0; c < NSTAGE; c++) {
        CP_WAIT1();
        __syncthreads();
        compute(c);
        __syncthreads();
        if (c + 2 < NSTAGE) fill(c + 2);
        CP_COMMIT();
    }

    // epilogue
#pragma unroll
    for (int mt = 0; mt < 4; mt++) {
        int m = m0 + wm + mt * 16 + (lane >> 2);
#pragma unroll
        for (int nt = 0; nt < 4; nt++) {
            int n = n0 + wn + nt * 8 + (lane & 3) * 2;
            if (EPI == 0) {
                float bx = bias[n], by = bias[n + 1];
                *(float2*)&Cf[(size_t)m * Nsz + n] =
                    make_float2(acc[mt][nt][0] + bx, acc[mt][nt][1] + by);
                *(float2*)&Cf[(size_t)(m + 8) * Nsz + n] =
                    make_float2(acc[mt][nt][2] + bx, acc[mt][nt][3] + by);
            } else {
                float sc = (n < DIMSZ) ? SCALE : 1.0f;   // fold softmax scale into Q
                u32 hp, lp;
                split2(acc[mt][nt][0] * sc, acc[mt][nt][1] * sc, hp, lp);
                *(u32*)(Ch + (size_t)m * Nsz + n) = hp;
                *(u32*)(Cl + (size_t)m * Nsz + n) = lp;
                split2(acc[mt][nt][2] * sc, acc[mt][nt][3] * sc, hp, lp);
                *(u32*)(Ch + (size_t)(m + 8) * Nsz + n) = hp;
                *(u32*)(Cl + (size_t)(m + 8) * Nsz + n) = lp;
            }
        }
    }
}

// ===========================================================================
// Attention via mma.sync, 3-term split-bf16 (unchanged from R7).
// Block = 256 thr (8 warps), one (b,h,128-q-row tile). K/V cp.async double-buf.
// ===========================================================================
#define AROW 144
#define QTILE (128 * AROW)          /* 18432 */
#define KTILE (64 * AROW)           /* 9216 */
#define AKVB (4 * KTILE)            /* Kh,Kl,Vh,Vl = 36864 */
#define ASMEM (2 * QTILE + 2 * AKVB) /* 110592; x2 CTAs = 221184 */

__global__ __launch_bounds__(256, 2) void attn_mma(const u16* __restrict__ qh,
                                                   const u16* __restrict__ ql,
                                                   const u16* __restrict__ vth,
                                                   const u16* __restrict__ vtl,
                                                   const float* __restrict__ rpb,
                                                   u16* __restrict__ oh,
                                                   u16* __restrict__ ol) {
    extern __shared__ char smem[];
    const u32 smb = smem_u32(smem);
    const int t = threadIdx.x;
    const int w = t >> 5, lane = t & 31;
    const int i0 = blockIdx.x * 128, h = blockIdx.y, b = blockIdx.z;

    const int brow = ((lane >> 4) << 3) + (lane & 7);

    // ---- Q tile (128 rows) -> smem (cp.async) ----
    {
        const int frow = t >> 1, half = t & 1;
        const size_t qoff = (size_t)(b * NTOK + i0 + frow) * QKVN + h * DH + half * 32;
        const u32 doff = (u32)(frow * AROW + half * 64);
#pragma unroll
        for (int i = 0; i < 4; i++) {
            CP16(smb + doff + i * 16, qh + qoff + i * 8);
            CP16(smb + QTILE + doff + i * 16, ql + qoff + i * 8);
        }
        CP_COMMIT();
    }

    auto fillKV = [&](int jt) {
        const u32 base = smb + 2 * QTILE + (jt & 1) * AKVB;
        const int row = t >> 2, q4 = t & 3;
        const size_t koff = (size_t)(b * NTOK + jt * 64 + row) * QKVN + DIMSZ + h * DH + q4 * 16;
        const size_t voff = (size_t)((b * HEADS + h) * DH + row) * NTOK + jt * 64 + q4 * 16;
        const u32 doff = (u32)(row * AROW + q4 * 32);
        CP16(base + doff, qh + koff);
        CP16(base + doff + 16, qh + koff + 8);
        CP16(base + KTILE + doff, ql + koff);
        CP16(base + KTILE + doff + 16, ql + koff + 8);
        CP16(base + 2 * KTILE + doff, vth + voff);
        CP16(base + 2 * KTILE + doff + 16, vth + voff + 8);
        CP16(base + 3 * KTILE + doff, vtl + voff);
        CP16(base + 3 * KTILE + doff + 16, vtl + voff + 8);
    };

    fillKV(0); CP_COMMIT();

    // Q fragments (wait until Q group done; KV0 may still be in flight)
    CP_WAIT1();
    __syncthreads();
    u32 Aqh[4][4], Aql[4][4];
#pragma unroll
    for (int ks = 0; ks < 4; ks++) {
        u32 ra = smb + (u32)((w * 16 + (lane & 15)) * AROW) + ks * 32 + ((lane & 16) ? 16 : 0);
        ldsm_x4(ra, Aqh[ks]);
        ldsm_x4(ra + QTILE, Aql[ks]);
    }

    // online softmax state (rows rA = lane>>2, rB = rA+8 within warp's m16)
    float o[8][4];
#pragma unroll
    for (int nt = 0; nt < 8; nt++)
#pragma unroll
        for (int k = 0; k < 4; k++) o[nt][k] = 0.f;
    float mA = -1e30f, mB = -1e30f, lA = 0.f, lB = 0.f;

    const float* bp = rpb + ((size_t)(h * NTOK + i0 + w * 16 + (lane >> 2))) * NTOK + 2 * (lane & 3);

    for (int jt = 0; jt < 16; jt++) {
        CP_WAIT0();
        __syncthreads();
        if (jt + 1 < 16) { fillKV(jt + 1); CP_COMMIT(); }

        const u32 kb = smb + 2 * QTILE + (jt & 1) * AKVB;
        const u32 vb = kb + 2 * KTILE;

        // ---- S = Q K^T (3-term split, term-major) ----
        float s[8][4];
#pragma unroll
        for (int nt = 0; nt < 8; nt++)
#pragma unroll
            for (int k = 0; k < 4; k++) s[nt][k] = 0.f;
#pragma unroll
        for (int ks = 0; ks < 4; ks++) {
            u32 Bh[4][4], Bl[4][4];
            const u32 bkb = (u32)(ks * 32 + ((lane & 8) ? 16 : 0));
#pragma unroll
            for (int bt = 0; bt < 4; bt++) {
                u32 rb = kb + (u32)((bt * 16 + brow) * AROW) + bkb;
                ldsm_x4(rb, Bh[bt]);
                ldsm_x4(rb + KTILE, Bl[bt]);
            }
#pragma unroll
            for (int nt = 0; nt < 8; nt++)
                mma16816(s[nt], Aqh[ks],
                         Bh[nt >> 1][(nt & 1) * 2], Bh[nt >> 1][(nt & 1) * 2 + 1]);
#pragma unroll
            for (int nt = 0; nt < 8; nt++)
                mma16816(s[nt], Aqh[ks],
                         Bl[nt >> 1][(nt & 1) * 2], Bl[nt >> 1][(nt & 1) * 2 + 1]);
#pragma unroll
            for (int nt = 0; nt < 8; nt++)
                mma16816(s[nt], Aql[ks],
                         Bh[nt >> 1][(nt & 1) * 2], Bh[nt >> 1][(nt & 1) * 2 + 1]);
        }

        // ---- + bias, online softmax ----
        const float* bpj = bp + jt * 64;
        float tmA = -1e30f, tmB = -1e30f;
#pragma unroll
        for (int nt = 0; nt < 8; nt++) {
            float2 ba = *(const float2*)(bpj + nt * 8);
            float2 bb = *(const float2*)(bpj + 8 * NTOK + nt * 8);
            s[nt][0] += ba.x; s[nt][1] += ba.y;
            s[nt][2] += bb.x; s[nt][3] += bb.y;
            tmA = fmaxf(tmA, fmaxf(s[nt][0], s[nt][1]));
            tmB = fmaxf(tmB, fmaxf(s[nt][2], s[nt][3]));
        }
        tmA = fmaxf(tmA, __shfl_xor_sync(0xffffffffu, tmA, 1));
        tmA = fmaxf(tmA, __shfl_xor_sync(0xffffffffu, tmA, 2));
        tmB = fmaxf(tmB, __shfl_xor_sync(0xffffffffu, tmB, 1));
        tmB = fmaxf(tmB, __shfl_xor_sync(0xffffffffu, tmB, 2));
        float nmA = fmaxf(mA, tmA), nmB = fmaxf(mB, tmB);
        float facA = __expf(mA - nmA), facB = __expf(mB - nmB);
        mA = nmA; mB = nmB;
        float suA = 0.f, suB = 0.f;
#pragma unroll
        for (int nt = 0; nt < 8; nt++) {
            s[nt][0] = __expf(s[nt][0] - mA);
            s[nt][1] = __expf(s[nt][1] - mA);
            s[nt][2] = __expf(s[nt][2] - mB);
            s[nt][3] = __expf(s[nt][3] - mB);
            suA += s[nt][0] + s[nt][1];
            suB += s[nt][2] + s[nt][3];
            o[nt][0] *= facA; o[nt][1] *= facA;
            o[nt][2] *= facB; o[nt][3] *= facB;
        }
        suA += __shfl_xor_sync(0xffffffffu, suA, 1);
        suA += __shfl_xor_sync(0xffffffffu, suA, 2);
        suB += __shfl_xor_sync(0xffffffffu, suB, 1);
        suB += __shfl_xor_sync(0xffffffffu, suB, 2);
        lA = lA * facA + suA;
        lB = lB * facB + suB;

        // ---- P fragments (accumulator layout -> A layout), split hi/lo ----
        u32 Aph[4][4], Apl[4][4];
#pragma unroll
        for (int kt = 0; kt < 4; kt++) {
            split2(s[2 * kt][0], s[2 * kt][1], Aph[kt][0], Apl[kt][0]);
            split2(s[2 * kt][2], s[2 * kt][3], Aph[kt][1], Apl[kt][1]);
            split2(s[2 * kt + 1][0], s[2 * kt + 1][1], Aph[kt][2], Apl[kt][2]);
            split2(s[2 * kt + 1][2], s[2 * kt + 1][3], Aph[kt][3], Apl[kt][3]);
        }

        // ---- O += P V (3-term split, term-major), V^T in smem [d][j] ----
#pragma unroll
        for (int kt = 0; kt < 4; kt++) {
            u32 Bh[4][4], Bl[4][4];
            const u32 bkb = (u32)(kt * 32 + ((lane & 8) ? 16 : 0));
#pragma unroll
            for (int bt = 0; bt < 4; bt++) {
                u32 rb = vb + (u32)((bt * 16 + brow) * AROW) + bkb;
                ldsm_x4(rb, Bh[bt]);
                ldsm_x4(rb + KTILE, Bl[bt]);
            }
#pragma unroll
            for (int nt = 0; nt < 8; nt++)
                mma16816(o[nt], Aph[kt],
                         Bh[nt >> 1][(nt & 1) * 2], Bh[nt >> 1][(nt & 1) * 2 + 1]);
#pragma unroll
            for (int nt = 0; nt < 8; nt++)
                mma16816(o[nt], Aph[kt],
                         Bl[nt >> 1][(nt & 1) * 2], Bl[nt >> 1][(nt & 1) * 2 + 1]);
#pragma unroll
            for (int nt = 0; nt < 8; nt++)
                mma16816(o[nt], Apl[kt],
                         Bh[nt >> 1][(nt & 1) * 2], Bh[nt >> 1][(nt & 1) * 2 + 1]);
        }
    }

    // ---- epilogue: normalize, split, store ----
    float invA = 1.0f / lA, invB = 1.0f / lB;
    int rowA = b * NTOK + i0 + w * 16 + (lane >> 2);
#pragma unroll
    for (int nt = 0; nt < 8; nt++) {
        int col = h * DH + nt * 8 + 2 * (lane & 3);
        u32 hp, lp;
        split2(o[nt][0] * invA, o[nt][1] * invA, hp, lp);
        *(u32*)(oh + (size_t)rowA * DIMSZ + col) = hp;
        *(u32*)(ol + (size_t)rowA * DIMSZ + col) = lp;
        split2(o[nt][2] * invB, o[nt][3] * invB, hp, lp);
        *(u32*)(oh + (size_t)(rowA + 8) * DIMSZ + col) = hp;
        *(u32*)(ol + (size_t)(rowA + 8) * DIMSZ + col) = lp;
    }
}

// ---------------------------------------------------------------------------
extern "C" void kernel_launch(void* const* d_in, const int* in_sizes, int n_in,
                              void* d_out, int out_size) {
    const float* x    = (const float*)d_in[0];
    const float* rpb  = (const float*)d_in[1];
    const float* Wqkv = (const float*)d_in[2];
    const float* Wout = (const float*)d_in[3];
    const float* bout = (const float*)d_in[4];
    const float* lng  = (const float*)d_in[5];
    const float* lnb  = (const float*)d_in[6];
    float* out = (float*)d_out;

    u16 *xnh, *xnl, *wqh, *wql, *woh, *wol, *qkh, *qkl, *vth, *vtl, *ath, *atl;
    cudaGetSymbolAddress((void**)&xnh, g_xnh);
    cudaGetSymbolAddress((void**)&xnl, g_xnl);
    cudaGetSymbolAddress((void**)&wqh, g_wqh);
    cudaGetSymbolAddress((void**)&wql, g_wql);
    cudaGetSymbolAddress((void**)&woh, g_woh);
    cudaGetSymbolAddress((void**)&wol, g_wol);
    cudaGetSymbolAddress((void**)&qkh, g_qkvh);
    cudaGetSymbolAddress((void**)&qkl, g_qkvl);
    cudaGetSymbolAddress((void**)&vth, g_vth);
    cudaGetSymbolAddress((void**)&vtl, g_vtl);
    cudaGetSymbolAddress((void**)&ath, g_atth);
    cudaGetSymbolAddress((void**)&atl, g_attl);

    // 1) LN -> split bf16
    ln_kernel<<<NROWS, 256>>>(x, lng, lnb, xnh, xnl);

    // 1b) weight prep (transpose + split)
    wprep_kernel<<<dim3(QKVN / 32, DIMSZ / 32), 256>>>(Wqkv, wqh, wql, QKVN);
    wprep_kernel<<<dim3(DIMSZ / 32, DIMSZ / 32), 256>>>(Wout, woh, wol, DIMSZ);

    // 2) QKV projection (split-bf16 out, Q pre-scaled)
    cudaFuncSetAttribute(mma_gemm<1>, cudaFuncAttributeMaxDynamicSharedMemorySize, GEMM_SMEM);
    mma_gemm<1><<<dim3(QKVN / 128, NROWS / 256), 512, GEMM_SMEM>>>(
        xnh, xnl, wqh, wql, nullptr, nullptr, qkh, qkl, QKVN);

    // 2b) V transpose
    vtrans_kernel<<<dim3(NTOK / 64, HEADS, BATCH), 256>>>(qkh, qkl, vth, vtl);

    // 3) attention (tensor-core, split-bf16, 8 warps/CTA)
    cudaFuncSetAttribute(attn_mma, cudaFuncAttributeMaxDynamicSharedMemorySize, ASMEM);
    attn_mma<<<dim3(NTOK / 128, HEADS, BATCH), 256, ASMEM>>>(
        qkh, qkl, vth, vtl, rpb, ath, atl);

    // 4) output projection (fp32 out + bias)
    cudaFuncSetAttribute(mma_gemm<0>, cudaFuncAttributeMaxDynamicSharedMemorySize, GEMM_SMEM);
    mma_gemm<0><<<dim3(DIMSZ / 128, NROWS / 256), 512, GEMM_SMEM>>>(
        ath, atl, woh, wol, bout, out, nullptr, nullptr, DIMSZ);
}

// round 10
// speedup vs baseline: 1.4284x; 1.4284x over previous
#include <cuda_runtime.h>
#include <cuda_fp16.h>
#include <cstdint>

#define DIMSZ 768
#define NTOK 1024
#define BATCH 8
#define HEADS 12
#define DH 64
#define NROWS (BATCH * NTOK)      /* 8192 */
#define QKVN (3 * DIMSZ)          /* 2304 */
#define SCALE 0.125f              /* DH^-0.5 */

typedef unsigned short u16;
typedef uint32_t u32;

// ---------------- scratch (device globals, allocation-free) ----------------
__device__ u16 g_xnh[NROWS * DIMSZ];     // LN out, fp16 hi
__device__ u16 g_xnl[NROWS * DIMSZ];     // LN out, fp16 lo
__device__ u16 g_wqh[QKVN * DIMSZ];      // Wqkv^T fp16 (single)
__device__ u16 g_woh[DIMSZ * DIMSZ];     // Wout^T fp16 (single)
__device__ u16 g_qkvh[NROWS * QKVN];     // qkv fp16 hi
__device__ u16 g_qkvl[NROWS * QKVN];     // qkv fp16 lo
__device__ u16 g_vth[BATCH * HEADS * DH * NTOK];   // V^T fp16 (hi only)
__device__ u16 g_atth[NROWS * DIMSZ];
__device__ u16 g_attl[NROWS * DIMSZ];

// ---------------- helpers ----------------
__device__ __forceinline__ u32 smem_u32(const void* p) {
    u32 a;
    asm("{ .reg .u64 t; cvta.to.shared.u64 t, %1; cvt.u32.u64 %0, t; }" : "=r"(a) : "l"(p));
    return a;
}
__device__ __forceinline__ void ldsm_x4(u32 addr, u32* r) {
    asm volatile("ldmatrix.sync.aligned.m8n8.x4.shared.b16 {%0,%1,%2,%3}, [%4];"
                 : "=r"(r[0]), "=r"(r[1]), "=r"(r[2]), "=r"(r[3]) : "r"(addr));
}
__device__ __forceinline__ void mma16816(float* c, const u32* a, u32 b0, u32 b1) {
    asm volatile("mma.sync.aligned.m16n8k16.row.col.f32.f16.f16.f32 "
                 "{%0,%1,%2,%3}, {%4,%5,%6,%7}, {%8,%9}, {%0,%1,%2,%3};"
                 : "+f"(c[0]), "+f"(c[1]), "+f"(c[2]), "+f"(c[3])
                 : "r"(a[0]), "r"(a[1]), "r"(a[2]), "r"(a[3]), "r"(b0), "r"(b1));
}
#define CP16(dst, src) \
    asm volatile("cp.async.cg.shared.global [%0], [%1], 16;" :: "r"(dst), "l"(src))
#define CP_COMMIT() asm volatile("cp.async.commit_group;" ::: "memory")
#define CP_WAIT0()  asm volatile("cp.async.wait_group 0;" ::: "memory")
#define CP_WAIT1()  asm volatile("cp.async.wait_group 1;" ::: "memory")

__device__ __forceinline__ void splith(float x, u16& h, u16& l) {
    __half hh = __float2half_rn(x);
    float hf = __half2float(hh);
    __half lb = __float2half_rn(x - hf);
    h = __half_as_ushort(hh);
    l = __half_as_ushort(lb);
}
__device__ __forceinline__ void split2h(float a, float b, u32& hp, u32& lp) {
    u16 ha, la, hb, lb;
    splith(a, ha, la);
    splith(b, hb, lb);
    hp = (u32)ha | ((u32)hb << 16);
    lp = (u32)la | ((u32)lb << 16);
}
__device__ __forceinline__ u32 pack2h(float a, float b) {
    __half2 v = __floats2half2_rn(a, b);
    return *(u32*)&v;
}

// ===========================================================================
// LayerNorm -> split fp16 hi/lo
// ===========================================================================
__global__ __launch_bounds__(256) void ln_kernel(const float* __restrict__ x,
                                                 const float* __restrict__ gamma,
                                                 const float* __restrict__ beta,
                                                 u16* __restrict__ yh,
                                                 u16* __restrict__ yl) {
    int row = blockIdx.x;
    int t = threadIdx.x;
    __shared__ float sv[DIMSZ];
    __shared__ float sb[8], ssb[8];
    __shared__ float smu, srstd;
    const float* xr = x + (size_t)row * DIMSZ;
    float v0 = xr[t], v1 = xr[t + 256], v2 = xr[t + 512];
    float s = v0 + v1 + v2;
    float ss = v0 * v0 + v1 * v1 + v2 * v2;
#pragma unroll
    for (int o = 16; o > 0; o >>= 1) {
        s += __shfl_xor_sync(0xffffffffu, s, o);
        ss += __shfl_xor_sync(0xffffffffu, ss, o);
    }
    if ((t & 31) == 0) { sb[t >> 5] = s; ssb[t >> 5] = ss; }
    __syncthreads();
    if (t == 0) {
        float S = 0.f, SS = 0.f;
#pragma unroll
        for (int i = 0; i < 8; i++) { S += sb[i]; SS += ssb[i]; }
        float mu = S * (1.0f / DIMSZ);
        float var = SS * (1.0f / DIMSZ) - mu * mu;
        smu = mu;
        srstd = rsqrtf(var + 1e-5f);
    }
    __syncthreads();
    float mu = smu, rstd = srstd;
    sv[t]       = (v0 - mu) * rstd * gamma[t]       + beta[t];
    sv[t + 256] = (v1 - mu) * rstd * gamma[t + 256] + beta[t + 256];
    sv[t + 512] = (v2 - mu) * rstd * gamma[t + 512] + beta[t + 512];
    __syncthreads();
    u32* oh = (u32*)(yh + (size_t)row * DIMSZ);
    u32* ol = (u32*)(yl + (size_t)row * DIMSZ);
    for (int p = t; p < DIMSZ / 2; p += 256) {
        u32 hp, lp;
        split2h(sv[2 * p], sv[2 * p + 1], hp, lp);
        oh[p] = hp;
        ol[p] = lp;
    }
}

// ===========================================================================
// Weight transpose to single fp16: W[768][N] -> Wt [N][768]
// ===========================================================================
__global__ __launch_bounds__(256) void wprep_kernel(const float* __restrict__ W,
                                                    u16* __restrict__ Wth,
                                                    int Nsz) {
    __shared__ float sm[32][33];
    int tx = threadIdx.x & 31, ty = threadIdx.x >> 5;   // 32 x 8
    int n0 = blockIdx.x * 32, k0 = blockIdx.y * 32;
#pragma unroll
    for (int i = 0; i < 4; i++)
        sm[ty + i * 8][tx] = W[(size_t)(k0 + ty + i * 8) * Nsz + n0 + tx];
    __syncthreads();
#pragma unroll
    for (int i = 0; i < 4; i++) {
        int n = n0 + ty + i * 8, k = k0 + tx;
        __half hv = __float2half_rn(sm[tx][ty + i * 8]);
        Wth[(size_t)n * DIMSZ + k] = __half_as_ushort(hv);
    }
}

// ===========================================================================
// V transpose (hi only): qkv V part [b][j][h*64+d] -> vt [b][h][d][j]
// ===========================================================================
__global__ __launch_bounds__(256) void vtrans_kernel(const u16* __restrict__ qh,
                                                     u16* __restrict__ vh) {
    __shared__ u16 sm[64][66];
    int t = threadIdx.x;
    int j0 = blockIdx.x * 64, h = blockIdx.y, b = blockIdx.z;
#pragma unroll
    for (int i = 0; i < 8; i++) {
        int id = t + i * 256;          // 0..2047
        int jj = id >> 5, dp = id & 31;
        u32 v = *(const u32*)(qh + (size_t)(b * NTOK + j0 + jj) * QKVN +
                              2 * DIMSZ + h * DH + dp * 2);
        sm[jj][2 * dp] = (u16)v;
        sm[jj][2 * dp + 1] = (u16)(v >> 16);
    }
    __syncthreads();
#pragma unroll
    for (int i = 0; i < 8; i++) {
        int id = t + i * 256;
        int d = id >> 5, jp = id & 31;
        u32 v = (u32)sm[2 * jp][d] | ((u32)sm[2 * jp + 1][d] << 16);
        *(u32*)(vh + ((size_t)((b * HEADS + h) * DH + d)) * NTOK + j0 + 2 * jp) = v;
    }
}

// ===========================================================================
// fp16 2-term GEMM: C[M,N] = (Ah+Al)[M,768] @ B[N,768]^T (+bias)
// CTA 128x128, 512 thr (16 warps, 32x32 tiles), KC=64, NBUF=3 cp.async.
// EPI 0: fp32 out + bias.  EPI 1: split fp16 out, SCALE folded on n<768.
// ===========================================================================
#define TROW 144                  /* 64 fp16 (128B) + 16B pad */
#define TILE (128 * TROW)         /* 18432 */
#define STAGE (3 * TILE)          /* 55296: Ah, Al, B */
#define NBUF 3
#define GEMM_SMEM (NBUF * STAGE)  /* 165888 */
#define KC 64
#define NSTAGE (DIMSZ / KC)       /* 12 */
#define B_OFF (2 * TILE)

template <int EPI>
__global__ __launch_bounds__(512, 1) void mma_gemm(const u16* __restrict__ Ah,
                                                   const u16* __restrict__ Al,
                                                   const u16* __restrict__ Bh,
                                                   const float* __restrict__ bias,
                                                   float* __restrict__ Cf,
                                                   u16* __restrict__ Ch,
                                                   u16* __restrict__ Cl,
                                                   int Nsz) {
    extern __shared__ char smem[];
    const u32 smb = smem_u32(smem);
    const int t = threadIdx.x;
    const int wid = t >> 5, lane = t & 31;
    const int m0 = blockIdx.y * 128, n0 = blockIdx.x * 128;
    const int wm = (wid >> 2) * 32, wn = (wid & 3) * 32;

    float acc[2][4][4];
#pragma unroll
    for (int i = 0; i < 2; i++)
#pragma unroll
        for (int j = 0; j < 4; j++)
#pragma unroll
            for (int k = 0; k < 4; k++) acc[i][j][k] = 0.f;

    const int frow = t >> 2;          // 0..127
    const int q4 = t & 3;             // 16-elem quarter

    auto fill = [&](int c) {
        const u32 base = smb + (c % NBUF) * STAGE;
        const size_t aoff = (size_t)(m0 + frow) * DIMSZ + c * KC + q4 * 16;
        const size_t boff = (size_t)(n0 + frow) * DIMSZ + c * KC + q4 * 16;
        const u32 doff = (u32)(frow * TROW + q4 * 32);
        CP16(base + doff, Ah + aoff);
        CP16(base + doff + 16, Ah + aoff + 8);
        CP16(base + TILE + doff, Al + aoff);
        CP16(base + TILE + doff + 16, Al + aoff + 8);
        CP16(base + B_OFF + doff, Bh + boff);
        CP16(base + B_OFF + doff + 16, Bh + boff + 8);
    };

    const int brow = ((lane >> 4) << 3) + (lane & 7);

    auto compute = [&](int c) {
        const u32 base = smb + (c % NBUF) * STAGE;
#pragma unroll
        for (int ks = 0; ks < 4; ks++) {
            u32 Ahf[2][4], Alf[2][4], Bhf[2][4];
            const u32 akb = (u32)(ks * 32 + ((lane & 16) ? 16 : 0));
#pragma unroll
            for (int mt = 0; mt < 2; mt++) {
                u32 ra = base + (u32)((wm + mt * 16 + (lane & 15)) * TROW) + akb;
                ldsm_x4(ra, Ahf[mt]);
                ldsm_x4(ra + TILE, Alf[mt]);
            }
            const u32 bkb = (u32)(ks * 32 + ((lane & 8) ? 16 : 0));
#pragma unroll
            for (int bt = 0; bt < 2; bt++) {
                u32 rb = base + B_OFF + (u32)((wn + bt * 16 + brow) * TROW) + bkb;
                ldsm_x4(rb, Bhf[bt]);
            }
#pragma unroll
            for (int mt = 0; mt < 2; mt++)
#pragma unroll
                for (int nt = 0; nt < 4; nt++)
                    mma16816(acc[mt][nt], Ahf[mt],
                             Bhf[nt >> 1][(nt & 1) * 2], Bhf[nt >> 1][(nt & 1) * 2 + 1]);
#pragma unroll
            for (int mt = 0; mt < 2; mt++)
#pragma unroll
                for (int nt = 0; nt < 4; nt++)
                    mma16816(acc[mt][nt], Alf[mt],
                             Bhf[nt >> 1][(nt & 1) * 2], Bhf[nt >> 1][(nt & 1) * 2 + 1]);
        }
    };

    fill(0); CP_COMMIT();
    fill(1); CP_COMMIT();
    for (int c = 0; c < NSTAGE; c++) {
        CP_WAIT1();
        __syncthreads();
        if (c + 2 < NSTAGE) fill(c + 2);
        CP_COMMIT();
        compute(c);
    }

    // epilogue
#pragma unroll
    for (int mt = 0; mt < 2; mt++) {
        int m = m0 + wm + mt * 16 + (lane >> 2);
#pragma unroll
        for (int nt = 0; nt < 4; nt++) {
            int n = n0 + wn + nt * 8 + (lane & 3) * 2;
            if (EPI == 0) {
                float bx = bias[n], by = bias[n + 1];
                *(float2*)&Cf[(size_t)m * Nsz + n] =
                    make_float2(acc[mt][nt][0] + bx, acc[mt][nt][1] + by);
                *(float2*)&Cf[(size_t)(m + 8) * Nsz + n] =
                    make_float2(acc[mt][nt][2] + bx, acc[mt][nt][3] + by);
            } else {
                float sc = (n < DIMSZ) ? SCALE : 1.0f;
                u32 hp, lp;
                split2h(acc[mt][nt][0] * sc, acc[mt][nt][1] * sc, hp, lp);
                *(u32*)(Ch + (size_t)m * Nsz + n) = hp;
                *(u32*)(Cl + (size_t)m * Nsz + n) = lp;
                split2h(acc[mt][nt][2] * sc, acc[mt][nt][3] * sc, hp, lp);
                *(u32*)(Ch + (size_t)(m + 8) * Nsz + n) = hp;
                *(u32*)(Cl + (size_t)(m + 8) * Nsz + n) = lp;
            }
        }
    }
}

// ===========================================================================
// Attention via fp16 2-term mma.sync: S = (Qh+Ql)K,  O = (Ph+Pl)V.
// Block = 256 thr (8 warps), one (b,h,128-q-row tile). K/V cp.async double-buf.
// ===========================================================================
#define AROW 144
#define QTILE (128 * AROW)          /* 18432 */
#define KTILE (64 * AROW)           /* 9216 */
#define AKVB (2 * KTILE)            /* Kh,Vh = 18432 */
#define ASMEM (2 * QTILE + 2 * AKVB) /* 73728; x2 CTAs = 147456 */

__global__ __launch_bounds__(256, 2) void attn_mma(const u16* __restrict__ qh,
                                                   const u16* __restrict__ ql,
                                                   const u16* __restrict__ vth,
                                                   const float* __restrict__ rpb,
                                                   u16* __restrict__ oh,
                                                   u16* __restrict__ ol) {
    extern __shared__ char smem[];
    const u32 smb = smem_u32(smem);
    const int t = threadIdx.x;
    const int w = t >> 5, lane = t & 31;
    const int i0 = blockIdx.x * 128, h = blockIdx.y, b = blockIdx.z;

    const int brow = ((lane >> 4) << 3) + (lane & 7);

    // ---- Q tile (128 rows, hi+lo) -> smem ----
    {
        const int frow = t >> 1, half = t & 1;
        const size_t qoff = (size_t)(b * NTOK + i0 + frow) * QKVN + h * DH + half * 32;
        const u32 doff = (u32)(frow * AROW + half * 64);
#pragma unroll
        for (int i = 0; i < 4; i++) {
            CP16(smb + doff + i * 16, qh + qoff + i * 8);
            CP16(smb + QTILE + doff + i * 16, ql + qoff + i * 8);
        }
        CP_COMMIT();
    }

    auto fillKV = [&](int jt) {
        const u32 base = smb + 2 * QTILE + (jt & 1) * AKVB;
        const int row = t >> 2, q4 = t & 3;
        const size_t koff = (size_t)(b * NTOK + jt * 64 + row) * QKVN + DIMSZ + h * DH + q4 * 16;
        const size_t voff = (size_t)((b * HEADS + h) * DH + row) * NTOK + jt * 64 + q4 * 16;
        const u32 doff = (u32)(row * AROW + q4 * 32);
        CP16(base + doff, qh + koff);
        CP16(base + doff + 16, qh + koff + 8);
        CP16(base + KTILE + doff, vth + voff);
        CP16(base + KTILE + doff + 16, vth + voff + 8);
    };

    fillKV(0); CP_COMMIT();

    CP_WAIT1();
    __syncthreads();
    u32 Aqh[4][4], Aql[4][4];
#pragma unroll
    for (int ks = 0; ks < 4; ks++) {
        u32 ra = smb + (u32)((w * 16 + (lane & 15)) * AROW) + ks * 32 + ((lane & 16) ? 16 : 0);
        ldsm_x4(ra, Aqh[ks]);
        ldsm_x4(ra + QTILE, Aql[ks]);
    }

    float o[8][4];
#pragma unroll
    for (int nt = 0; nt < 8; nt++)
#pragma unroll
        for (int k = 0; k < 4; k++) o[nt][k] = 0.f;
    float mA = -1e30f, mB = -1e30f, lA = 0.f, lB = 0.f;

    const float* bp = rpb + ((size_t)(h * NTOK + i0 + w * 16 + (lane >> 2))) * NTOK + 2 * (lane & 3);

    for (int jt = 0; jt < 16; jt++) {
        CP_WAIT0();
        __syncthreads();
        if (jt + 1 < 16) { fillKV(jt + 1); CP_COMMIT(); }

        const u32 kb = smb + 2 * QTILE + (jt & 1) * AKVB;
        const u32 vb = kb + KTILE;

        // ---- S = Q K^T (2-term) ----
        float s[8][4];
#pragma unroll
        for (int nt = 0; nt < 8; nt++)
#pragma unroll
            for (int k = 0; k < 4; k++) s[nt][k] = 0.f;
#pragma unroll
        for (int ks = 0; ks < 4; ks++) {
            u32 Bf[4][4];
            const u32 bkb = (u32)(ks * 32 + ((lane & 8) ? 16 : 0));
#pragma unroll
            for (int bt = 0; bt < 4; bt++) {
                u32 rb = kb + (u32)((bt * 16 + brow) * AROW) + bkb;
                ldsm_x4(rb, Bf[bt]);
            }
#pragma unroll
            for (int nt = 0; nt < 8; nt++)
                mma16816(s[nt], Aqh[ks],
                         Bf[nt >> 1][(nt & 1) * 2], Bf[nt >> 1][(nt & 1) * 2 + 1]);
#pragma unroll
            for (int nt = 0; nt < 8; nt++)
                mma16816(s[nt], Aql[ks],
                         Bf[nt >> 1][(nt & 1) * 2], Bf[nt >> 1][(nt & 1) * 2 + 1]);
        }

        // ---- + bias, online softmax ----
        const float* bpj = bp + jt * 64;
        float tmA = -1e30f, tmB = -1e30f;
#pragma unroll
        for (int nt = 0; nt < 8; nt++) {
            float2 ba = *(const float2*)(bpj + nt * 8);
            float2 bb = *(const float2*)(bpj + 8 * NTOK + nt * 8);
            s[nt][0] += ba.x; s[nt][1] += ba.y;
            s[nt][2] += bb.x; s[nt][3] += bb.y;
            tmA = fmaxf(tmA, fmaxf(s[nt][0], s[nt][1]));
            tmB = fmaxf(tmB, fmaxf(s[nt][2], s[nt][3]));
        }
        tmA = fmaxf(tmA, __shfl_xor_sync(0xffffffffu, tmA, 1));
        tmA = fmaxf(tmA, __shfl_xor_sync(0xffffffffu, tmA, 2));
        tmB = fmaxf(tmB, __shfl_xor_sync(0xffffffffu, tmB, 1));
        tmB = fmaxf(tmB, __shfl_xor_sync(0xffffffffu, tmB, 2));
        float nmA = fmaxf(mA, tmA), nmB = fmaxf(mB, tmB);
        float facA = __expf(mA - nmA), facB = __expf(mB - nmB);
        mA = nmA; mB = nmB;
        float suA = 0.f, suB = 0.f;
#pragma unroll
        for (int nt = 0; nt < 8; nt++) {
            s[nt][0] = __expf(s[nt][0] - mA);
            s[nt][1] = __expf(s[nt][1] - mA);
            s[nt][2] = __expf(s[nt][2] - mB);
            s[nt][3] = __expf(s[nt][3] - mB);
            suA += s[nt][0] + s[nt][1];
            suB += s[nt][2] + s[nt][3];
            o[nt][0] *= facA; o[nt][1] *= facA;
            o[nt][2] *= facB; o[nt][3] *= facB;
        }
        suA += __shfl_xor_sync(0xffffffffu, suA, 1);
        suA += __shfl_xor_sync(0xffffffffu, suA, 2);
        suB += __shfl_xor_sync(0xffffffffu, suB, 1);
        suB += __shfl_xor_sync(0xffffffffu, suB, 2);
        lA = lA * facA + suA;
        lB = lB * facB + suB;

        // ---- P fragments (split fp16 hi/lo) ----
        u32 Aph[4][4], Apl[4][4];
#pragma unroll
        for (int kt = 0; kt < 4; kt++) {
            split2h(s[2 * kt][0], s[2 * kt][1], Aph[kt][0], Apl[kt][0]);
            split2h(s[2 * kt][2], s[2 * kt][3], Aph[kt][1], Apl[kt][1]);
            split2h(s[2 * kt + 1][0], s[2 * kt + 1][1], Aph[kt][2], Apl[kt][2]);
            split2h(s[2 * kt + 1][2], s[2 * kt + 1][3], Aph[kt][3], Apl[kt][3]);
        }

        // ---- O += P V (2-term), V^T in smem [d][j] ----
#pragma unroll
        for (int kt = 0; kt < 4; kt++) {
            u32 Bf[4][4];
            const u32 bkb = (u32)(kt * 32 + ((lane & 8) ? 16 : 0));
#pragma unroll
            for (int bt = 0; bt < 4; bt++) {
                u32 rb = vb + (u32)((bt * 16 + brow) * AROW) + bkb;
                ldsm_x4(rb, Bf[bt]);
            }
#pragma unroll
            for (int nt = 0; nt < 8; nt++)
                mma16816(o[nt], Aph[kt],
                         Bf[nt >> 1][(nt & 1) * 2], Bf[nt >> 1][(nt & 1) * 2 + 1]);
#pragma unroll
            for (int nt = 0; nt < 8; nt++)
                mma16816(o[nt], Apl[kt],
                         Bf[nt >> 1][(nt & 1) * 2], Bf[nt >> 1][(nt & 1) * 2 + 1]);
        }
    }

    // ---- epilogue: normalize, split, store ----
    float invA = 1.0f / lA, invB = 1.0f / lB;
    int rowA = b * NTOK + i0 + w * 16 + (lane >> 2);
#pragma unroll
    for (int nt = 0; nt < 8; nt++) {
        int col = h * DH + nt * 8 + 2 * (lane & 3);
        u32 hp, lp;
        split2h(o[nt][0] * invA, o[nt][1] * invA, hp, lp);
        *(u32*)(oh + (size_t)rowA * DIMSZ + col) = hp;
        *(u32*)(ol + (size_t)rowA * DIMSZ + col) = lp;
        split2h(o[nt][2] * invB, o[nt][3] * invB, hp, lp);
        *(u32*)(oh + (size_t)(rowA + 8) * DIMSZ + col) = hp;
        *(u32*)(ol + (size_t)(rowA + 8) * DIMSZ + col) = lp;
    }
}

// ---------------------------------------------------------------------------
extern "C" void kernel_launch(void* const* d_in, const int* in_sizes, int n_in,
                              void* d_out, int out_size) {
    const float* x    = (const float*)d_in[0];
    const float* rpb  = (const float*)d_in[1];
    const float* Wqkv = (const float*)d_in[2];
    const float* Wout = (const float*)d_in[3];
    const float* bout = (const float*)d_in[4];
    const float* lng  = (const float*)d_in[5];
    const float* lnb  = (const float*)d_in[6];
    float* out = (float*)d_out;

    u16 *xnh, *xnl, *wqh, *woh, *qkh, *qkl, *vth, *ath, *atl;
    cudaGetSymbolAddress((void**)&xnh, g_xnh);
    cudaGetSymbolAddress((void**)&xnl, g_xnl);
    cudaGetSymbolAddress((void**)&wqh, g_wqh);
    cudaGetSymbolAddress((void**)&woh, g_woh);
    cudaGetSymbolAddress((void**)&qkh, g_qkvh);
    cudaGetSymbolAddress((void**)&qkl, g_qkvl);
    cudaGetSymbolAddress((void**)&vth, g_vth);
    cudaGetSymbolAddress((void**)&ath, g_atth);
    cudaGetSymbolAddress((void**)&atl, g_attl);

    // 1) LN -> split fp16
    ln_kernel<<<NROWS, 256>>>(x, lng, lnb, xnh, xnl);

    // 1b) weight prep (transpose, single fp16)
    wprep_kernel<<<dim3(QKVN / 32, DIMSZ / 32), 256>>>(Wqkv, wqh, QKVN);
    wprep_kernel<<<dim3(DIMSZ / 32, DIMSZ / 32), 256>>>(Wout, woh, DIMSZ);

    // 2) QKV projection (split fp16 out, Q pre-scaled)
    cudaFuncSetAttribute(mma_gemm<1>, cudaFuncAttributeMaxDynamicSharedMemorySize, GEMM_SMEM);
    mma_gemm<1><<<dim3(QKVN / 128, NROWS / 128), 512, GEMM_SMEM>>>(
        xnh, xnl, wqh, nullptr, nullptr, qkh, qkl, QKVN);

    // 2b) V transpose (hi only)
    vtrans_kernel<<<dim3(NTOK / 64, HEADS, BATCH), 256>>>(qkh, vth);

    // 3) attention (fp16 2-term)
    cudaFuncSetAttribute(attn_mma, cudaFuncAttributeMaxDynamicSharedMemorySize, ASMEM);
    attn_mma<<<dim3(NTOK / 128, HEADS, BATCH), 256, ASMEM>>>(
        qkh, qkl, vth, rpb, ath, atl);

    // 4) output projection (fp32 out + bias)
    cudaFuncSetAttribute(mma_gemm<0>, cudaFuncAttributeMaxDynamicSharedMemorySize, GEMM_SMEM);
    mma_gemm<0><<<dim3(DIMSZ / 128, NROWS / 128), 512, GEMM_SMEM>>>(
        ath, atl, woh, bout, out, nullptr, nullptr, DIMSZ);
}

// round 11
// speedup vs baseline: 1.6611x; 1.1629x over previous
#include <cuda_runtime.h>
#include <cuda_fp16.h>
#include <cstdint>

#define DIMSZ 768
#define NTOK 1024
#define BATCH 8
#define HEADS 12
#define DH 64
#define NROWS (BATCH * NTOK)      /* 8192 */
#define QKVN (3 * DIMSZ)          /* 2304 */
#define SCALE 0.125f              /* DH^-0.5 */

typedef unsigned short u16;
typedef uint32_t u32;

// ---------------- scratch (device globals, allocation-free) ----------------
__device__ u16 g_xnh[NROWS * DIMSZ];     // LN out, fp16 hi
__device__ u16 g_xnl[NROWS * DIMSZ];     // LN out, fp16 lo
__device__ u16 g_wqh[QKVN * DIMSZ];      // Wqkv^T fp16
__device__ u16 g_woh[DIMSZ * DIMSZ];     // Wout^T fp16
__device__ u16 g_qkvh[NROWS * QKVN];     // qkv fp16 hi
__device__ u16 g_qkvl[NROWS * QKVN];     // qkv fp16 lo
__device__ u16 g_vth[BATCH * HEADS * DH * NTOK];   // V^T fp16
__device__ u16 g_atth[NROWS * DIMSZ];    // attention out, single fp16

// ---------------- helpers ----------------
__device__ __forceinline__ u32 smem_u32(const void* p) {
    u32 a;
    asm("{ .reg .u64 t; cvta.to.shared.u64 t, %1; cvt.u32.u64 %0, t; }" : "=r"(a) : "l"(p));
    return a;
}
__device__ __forceinline__ void ldsm_x4(u32 addr, u32* r) {
    asm volatile("ldmatrix.sync.aligned.m8n8.x4.shared.b16 {%0,%1,%2,%3}, [%4];"
                 : "=r"(r[0]), "=r"(r[1]), "=r"(r[2]), "=r"(r[3]) : "r"(addr));
}
__device__ __forceinline__ void mma16816(float* c, const u32* a, u32 b0, u32 b1) {
    asm volatile("mma.sync.aligned.m16n8k16.row.col.f32.f16.f16.f32 "
                 "{%0,%1,%2,%3}, {%4,%5,%6,%7}, {%8,%9}, {%0,%1,%2,%3};"
                 : "+f"(c[0]), "+f"(c[1]), "+f"(c[2]), "+f"(c[3])
                 : "r"(a[0]), "r"(a[1]), "r"(a[2]), "r"(a[3]), "r"(b0), "r"(b1));
}
#define CP16(dst, src) \
    asm volatile("cp.async.cg.shared.global [%0], [%1], 16;" :: "r"(dst), "l"(src))
#define CP_COMMIT() asm volatile("cp.async.commit_group;" ::: "memory")
#define CP_WAIT0()  asm volatile("cp.async.wait_group 0;" ::: "memory")
#define CP_WAIT1()  asm volatile("cp.async.wait_group 1;" ::: "memory")

__device__ __forceinline__ void splith(float x, u16& h, u16& l) {
    __half hh = __float2half_rn(x);
    float hf = __half2float(hh);
    __half lb = __float2half_rn(x - hf);
    h = __half_as_ushort(hh);
    l = __half_as_ushort(lb);
}
__device__ __forceinline__ void split2h(float a, float b, u32& hp, u32& lp) {
    u16 ha, la, hb, lb;
    splith(a, ha, la);
    splith(b, hb, lb);
    hp = (u32)ha | ((u32)hb << 16);
    lp = (u32)la | ((u32)lb << 16);
}
__device__ __forceinline__ u32 pack2h(float a, float b) {
    __half2 v = __floats2half2_rn(a, b);
    return *(u32*)&v;
}

// ===========================================================================
// LayerNorm -> split fp16 hi/lo
// ===========================================================================
__global__ __launch_bounds__(256) void ln_kernel(const float* __restrict__ x,
                                                 const float* __restrict__ gamma,
                                                 const float* __restrict__ beta,
                                                 u16* __restrict__ yh,
                                                 u16* __restrict__ yl) {
    int row = blockIdx.x;
    int t = threadIdx.x;
    __shared__ float sv[DIMSZ];
    __shared__ float sb[8], ssb[8];
    __shared__ float smu, srstd;
    const float* xr = x + (size_t)row * DIMSZ;
    float v0 = xr[t], v1 = xr[t + 256], v2 = xr[t + 512];
    float s = v0 + v1 + v2;
    float ss = v0 * v0 + v1 * v1 + v2 * v2;
#pragma unroll
    for (int o = 16; o > 0; o >>= 1) {
        s += __shfl_xor_sync(0xffffffffu, s, o);
        ss += __shfl_xor_sync(0xffffffffu, ss, o);
    }
    if ((t & 31) == 0) { sb[t >> 5] = s; ssb[t >> 5] = ss; }
    __syncthreads();
    if (t == 0) {
        float S = 0.f, SS = 0.f;
#pragma unroll
        for (int i = 0; i < 8; i++) { S += sb[i]; SS += ssb[i]; }
        float mu = S * (1.0f / DIMSZ);
        float var = SS * (1.0f / DIMSZ) - mu * mu;
        smu = mu;
        srstd = rsqrtf(var + 1e-5f);
    }
    __syncthreads();
    float mu = smu, rstd = srstd;
    sv[t]       = (v0 - mu) * rstd * gamma[t]       + beta[t];
    sv[t + 256] = (v1 - mu) * rstd * gamma[t + 256] + beta[t + 256];
    sv[t + 512] = (v2 - mu) * rstd * gamma[t + 512] + beta[t + 512];
    __syncthreads();
    u32* oh = (u32*)(yh + (size_t)row * DIMSZ);
    u32* ol = (u32*)(yl + (size_t)row * DIMSZ);
    for (int p = t; p < DIMSZ / 2; p += 256) {
        u32 hp, lp;
        split2h(sv[2 * p], sv[2 * p + 1], hp, lp);
        oh[p] = hp;
        ol[p] = lp;
    }
}

// ===========================================================================
// Weight transpose to single fp16: W[768][N] -> Wt [N][768]
// ===========================================================================
__global__ __launch_bounds__(256) void wprep_kernel(const float* __restrict__ W,
                                                    u16* __restrict__ Wth,
                                                    int Nsz) {
    __shared__ float sm[32][33];
    int tx = threadIdx.x & 31, ty = threadIdx.x >> 5;   // 32 x 8
    int n0 = blockIdx.x * 32, k0 = blockIdx.y * 32;
#pragma unroll
    for (int i = 0; i < 4; i++)
        sm[ty + i * 8][tx] = W[(size_t)(k0 + ty + i * 8) * Nsz + n0 + tx];
    __syncthreads();
#pragma unroll
    for (int i = 0; i < 4; i++) {
        int n = n0 + ty + i * 8, k = k0 + tx;
        __half hv = __float2half_rn(sm[tx][ty + i * 8]);
        Wth[(size_t)n * DIMSZ + k] = __half_as_ushort(hv);
    }
}

// ===========================================================================
// V transpose (hi only): qkv V part [b][j][h*64+d] -> vt [b][h][d][j]
// ===========================================================================
__global__ __launch_bounds__(256) void vtrans_kernel(const u16* __restrict__ qh,
                                                     u16* __restrict__ vh) {
    __shared__ u16 sm[64][66];
    int t = threadIdx.x;
    int j0 = blockIdx.x * 64, h = blockIdx.y, b = blockIdx.z;
#pragma unroll
    for (int i = 0; i < 8; i++) {
        int id = t + i * 256;          // 0..2047
        int jj = id >> 5, dp = id & 31;
        u32 v = *(const u32*)(qh + (size_t)(b * NTOK + j0 + jj) * QKVN +
                              2 * DIMSZ + h * DH + dp * 2);
        sm[jj][2 * dp] = (u16)v;
        sm[jj][2 * dp + 1] = (u16)(v >> 16);
    }
    __syncthreads();
#pragma unroll
    for (int i = 0; i < 8; i++) {
        int id = t + i * 256;
        int d = id >> 5, jp = id & 31;
        u32 v = (u32)sm[2 * jp][d] | ((u32)sm[2 * jp + 1][d] << 16);
        *(u32*)(vh + ((size_t)((b * HEADS + h) * DH + d)) * NTOK + j0 + 2 * jp) = v;
    }
}

// ===========================================================================
// fp16 GEMM: C[M,N] = (Ah[+Al])[M,768] @ B[N,768]^T (+bias)
// CTA 128x128, 512 thr (16 warps, 32x32 tiles), KC=64, NBUF=3 cp.async.
// TERMS: 2 = A split 2-term, 1 = single A.
// EPI 0: fp32 out + bias.  EPI 1: split fp16 out, SCALE folded on n<768.
// ===========================================================================
#define TROW 144                  /* 64 fp16 (128B) + 16B pad */
#define TILE (128 * TROW)         /* 18432 */
#define STAGE (3 * TILE)          /* 55296: Ah, Al, B */
#define NBUF 3
#define GEMM_SMEM (NBUF * STAGE)  /* 165888 */
#define KC 64
#define NSTAGE (DIMSZ / KC)       /* 12 */
#define B_OFF (2 * TILE)

template <int EPI, int TERMS>
__global__ __launch_bounds__(512, 1) void mma_gemm(const u16* __restrict__ Ah,
                                                   const u16* __restrict__ Al,
                                                   const u16* __restrict__ Bh,
                                                   const float* __restrict__ bias,
                                                   float* __restrict__ Cf,
                                                   u16* __restrict__ Ch,
                                                   u16* __restrict__ Cl,
                                                   int Nsz) {
    extern __shared__ char smem[];
    const u32 smb = smem_u32(smem);
    const int t = threadIdx.x;
    const int wid = t >> 5, lane = t & 31;
    const int m0 = blockIdx.y * 128, n0 = blockIdx.x * 128;
    const int wm = (wid >> 2) * 32, wn = (wid & 3) * 32;

    float acc[2][4][4];
#pragma unroll
    for (int i = 0; i < 2; i++)
#pragma unroll
        for (int j = 0; j < 4; j++)
#pragma unroll
            for (int k = 0; k < 4; k++) acc[i][j][k] = 0.f;

    const int frow = t >> 2;          // 0..127
    const int q4 = t & 3;             // 16-elem quarter

    auto fill = [&](int c) {
        const u32 base = smb + (c % NBUF) * STAGE;
        const size_t aoff = (size_t)(m0 + frow) * DIMSZ + c * KC + q4 * 16;
        const size_t boff = (size_t)(n0 + frow) * DIMSZ + c * KC + q4 * 16;
        const u32 doff = (u32)(frow * TROW + q4 * 32);
        CP16(base + doff, Ah + aoff);
        CP16(base + doff + 16, Ah + aoff + 8);
        if (TERMS == 2) {
            CP16(base + TILE + doff, Al + aoff);
            CP16(base + TILE + doff + 16, Al + aoff + 8);
        }
        CP16(base + B_OFF + doff, Bh + boff);
        CP16(base + B_OFF + doff + 16, Bh + boff + 8);
    };

    const int brow = ((lane >> 4) << 3) + (lane & 7);

    auto compute = [&](int c) {
        const u32 base = smb + (c % NBUF) * STAGE;
#pragma unroll
        for (int ks = 0; ks < 4; ks++) {
            u32 Ahf[2][4], Alf[2][4], Bhf[2][4];
            const u32 akb = (u32)(ks * 32 + ((lane & 16) ? 16 : 0));
#pragma unroll
            for (int mt = 0; mt < 2; mt++) {
                u32 ra = base + (u32)((wm + mt * 16 + (lane & 15)) * TROW) + akb;
                ldsm_x4(ra, Ahf[mt]);
                if (TERMS == 2) ldsm_x4(ra + TILE, Alf[mt]);
            }
            const u32 bkb = (u32)(ks * 32 + ((lane & 8) ? 16 : 0));
#pragma unroll
            for (int bt = 0; bt < 2; bt++) {
                u32 rb = base + B_OFF + (u32)((wn + bt * 16 + brow) * TROW) + bkb;
                ldsm_x4(rb, Bhf[bt]);
            }
#pragma unroll
            for (int mt = 0; mt < 2; mt++)
#pragma unroll
                for (int nt = 0; nt < 4; nt++)
                    mma16816(acc[mt][nt], Ahf[mt],
                             Bhf[nt >> 1][(nt & 1) * 2], Bhf[nt >> 1][(nt & 1) * 2 + 1]);
            if (TERMS == 2) {
#pragma unroll
                for (int mt = 0; mt < 2; mt++)
#pragma unroll
                    for (int nt = 0; nt < 4; nt++)
                        mma16816(acc[mt][nt], Alf[mt],
                                 Bhf[nt >> 1][(nt & 1) * 2], Bhf[nt >> 1][(nt & 1) * 2 + 1]);
            }
        }
    };

    fill(0); CP_COMMIT();
    fill(1); CP_COMMIT();
    for (int c = 0; c < NSTAGE; c++) {
        CP_WAIT1();
        __syncthreads();
        if (c + 2 < NSTAGE) fill(c + 2);
        CP_COMMIT();
        compute(c);
    }

    // epilogue
#pragma unroll
    for (int mt = 0; mt < 2; mt++) {
        int m = m0 + wm + mt * 16 + (lane >> 2);
#pragma unroll
        for (int nt = 0; nt < 4; nt++) {
            int n = n0 + wn + nt * 8 + (lane & 3) * 2;
            if (EPI == 0) {
                float bx = bias[n], by = bias[n + 1];
                *(float2*)&Cf[(size_t)m * Nsz + n] =
                    make_float2(acc[mt][nt][0] + bx, acc[mt][nt][1] + by);
                *(float2*)&Cf[(size_t)(m + 8) * Nsz + n] =
                    make_float2(acc[mt][nt][2] + bx, acc[mt][nt][3] + by);
            } else {
                float sc = (n < DIMSZ) ? SCALE : 1.0f;
                u32 hp, lp;
                split2h(acc[mt][nt][0] * sc, acc[mt][nt][1] * sc, hp, lp);
                *(u32*)(Ch + (size_t)m * Nsz + n) = hp;
                *(u32*)(Cl + (size_t)m * Nsz + n) = lp;
                split2h(acc[mt][nt][2] * sc, acc[mt][nt][3] * sc, hp, lp);
                *(u32*)(Ch + (size_t)(m + 8) * Nsz + n) = hp;
                *(u32*)(Cl + (size_t)(m + 8) * Nsz + n) = lp;
            }
        }
    }
}

// ===========================================================================
// Attention: S = (Qh+Ql)K (2-term),  O = Ph V (1-term).
// Block = 256 thr (8 warps), one (b,h,128-q-row tile). K/V cp.async double-buf.
// Output: single fp16.
// ===========================================================================
#define AROW 144
#define QTILE (128 * AROW)          /* 18432 */
#define KTILE (64 * AROW)           /* 9216 */
#define AKVB (2 * KTILE)            /* Kh,Vh = 18432 */
#define ASMEM (2 * QTILE + 2 * AKVB) /* 73728; x2 CTAs = 147456 */

__global__ __launch_bounds__(256, 2) void attn_mma(const u16* __restrict__ qh,
                                                   const u16* __restrict__ ql,
                                                   const u16* __restrict__ vth,
                                                   const float* __restrict__ rpb,
                                                   u16* __restrict__ oh) {
    extern __shared__ char smem[];
    const u32 smb = smem_u32(smem);
    const int t = threadIdx.x;
    const int w = t >> 5, lane = t & 31;
    const int i0 = blockIdx.x * 128, h = blockIdx.y, b = blockIdx.z;

    const int brow = ((lane >> 4) << 3) + (lane & 7);

    // ---- Q tile (128 rows, hi+lo) -> smem ----
    {
        const int frow = t >> 1, half = t & 1;
        const size_t qoff = (size_t)(b * NTOK + i0 + frow) * QKVN + h * DH + half * 32;
        const u32 doff = (u32)(frow * AROW + half * 64);
#pragma unroll
        for (int i = 0; i < 4; i++) {
            CP16(smb + doff + i * 16, qh + qoff + i * 8);
            CP16(smb + QTILE + doff + i * 16, ql + qoff + i * 8);
        }
        CP_COMMIT();
    }

    auto fillKV = [&](int jt) {
        const u32 base = smb + 2 * QTILE + (jt & 1) * AKVB;
        const int row = t >> 2, q4 = t & 3;
        const size_t koff = (size_t)(b * NTOK + jt * 64 + row) * QKVN + DIMSZ + h * DH + q4 * 16;
        const size_t voff = (size_t)((b * HEADS + h) * DH + row) * NTOK + jt * 64 + q4 * 16;
        const u32 doff = (u32)(row * AROW + q4 * 32);
        CP16(base + doff, qh + koff);
        CP16(base + doff + 16, qh + koff + 8);
        CP16(base + KTILE + doff, vth + voff);
        CP16(base + KTILE + doff + 16, vth + voff + 8);
    };

    fillKV(0); CP_COMMIT();

    CP_WAIT1();
    __syncthreads();
    u32 Aqh[4][4], Aql[4][4];
#pragma unroll
    for (int ks = 0; ks < 4; ks++) {
        u32 ra = smb + (u32)((w * 16 + (lane & 15)) * AROW) + ks * 32 + ((lane & 16) ? 16 : 0);
        ldsm_x4(ra, Aqh[ks]);
        ldsm_x4(ra + QTILE, Aql[ks]);
    }

    float o[8][4];
#pragma unroll
    for (int nt = 0; nt < 8; nt++)
#pragma unroll
        for (int k = 0; k < 4; k++) o[nt][k] = 0.f;
    float mA = -1e30f, mB = -1e30f, lA = 0.f, lB = 0.f;

    const float* bp = rpb + ((size_t)(h * NTOK + i0 + w * 16 + (lane >> 2))) * NTOK + 2 * (lane & 3);

    for (int jt = 0; jt < 16; jt++) {
        CP_WAIT0();
        __syncthreads();
        if (jt + 1 < 16) { fillKV(jt + 1); CP_COMMIT(); }

        const u32 kb = smb + 2 * QTILE + (jt & 1) * AKVB;
        const u32 vb = kb + KTILE;

        // ---- S = Q K^T (2-term) ----
        float s[8][4];
#pragma unroll
        for (int nt = 0; nt < 8; nt++)
#pragma unroll
            for (int k = 0; k < 4; k++) s[nt][k] = 0.f;
#pragma unroll
        for (int ks = 0; ks < 4; ks++) {
            u32 Bf[4][4];
            const u32 bkb = (u32)(ks * 32 + ((lane & 8) ? 16 : 0));
#pragma unroll
            for (int bt = 0; bt < 4; bt++) {
                u32 rb = kb + (u32)((bt * 16 + brow) * AROW) + bkb;
                ldsm_x4(rb, Bf[bt]);
            }
#pragma unroll
            for (int nt = 0; nt < 8; nt++)
                mma16816(s[nt], Aqh[ks],
                         Bf[nt >> 1][(nt & 1) * 2], Bf[nt >> 1][(nt & 1) * 2 + 1]);
#pragma unroll
            for (int nt = 0; nt < 8; nt++)
                mma16816(s[nt], Aql[ks],
                         Bf[nt >> 1][(nt & 1) * 2], Bf[nt >> 1][(nt & 1) * 2 + 1]);
        }

        // ---- + bias, online softmax ----
        const float* bpj = bp + jt * 64;
        float tmA = -1e30f, tmB = -1e30f;
#pragma unroll
        for (int nt = 0; nt < 8; nt++) {
            float2 ba = *(const float2*)(bpj + nt * 8);
            float2 bb = *(const float2*)(bpj + 8 * NTOK + nt * 8);
            s[nt][0] += ba.x; s[nt][1] += ba.y;
            s[nt][2] += bb.x; s[nt][3] += bb.y;
            tmA = fmaxf(tmA, fmaxf(s[nt][0], s[nt][1]));
            tmB = fmaxf(tmB, fmaxf(s[nt][2], s[nt][3]));
        }
        tmA = fmaxf(tmA, __shfl_xor_sync(0xffffffffu, tmA, 1));
        tmA = fmaxf(tmA, __shfl_xor_sync(0xffffffffu, tmA, 2));
        tmB = fmaxf(tmB, __shfl_xor_sync(0xffffffffu, tmB, 1));
        tmB = fmaxf(tmB, __shfl_xor_sync(0xffffffffu, tmB, 2));
        float nmA = fmaxf(mA, tmA), nmB = fmaxf(mB, tmB);
        float facA = __expf(mA - nmA), facB = __expf(mB - nmB);
        mA = nmA; mB = nmB;
        float suA = 0.f, suB = 0.f;
#pragma unroll
        for (int nt = 0; nt < 8; nt++) {
            s[nt][0] = __expf(s[nt][0] - mA);
            s[nt][1] = __expf(s[nt][1] - mA);
            s[nt][2] = __expf(s[nt][2] - mB);
            s[nt][3] = __expf(s[nt][3] - mB);
            suA += s[nt][0] + s[nt][1];
            suB += s[nt][2] + s[nt][3];
            o[nt][0] *= facA; o[nt][1] *= facA;
            o[nt][2] *= facB; o[nt][3] *= facB;
        }
        suA += __shfl_xor_sync(0xffffffffu, suA, 1);
        suA += __shfl_xor_sync(0xffffffffu, suA, 2);
        suB += __shfl_xor_sync(0xffffffffu, suB, 1);
        suB += __shfl_xor_sync(0xffffffffu, suB, 2);
        lA = lA * facA + suA;
        lB = lB * facB + suB;

        // ---- P fragments (single fp16) ----
        u32 Aph[4][4];
#pragma unroll
        for (int kt = 0; kt < 4; kt++) {
            Aph[kt][0] = pack2h(s[2 * kt][0], s[2 * kt][1]);
            Aph[kt][1] = pack2h(s[2 * kt][2], s[2 * kt][3]);
            Aph[kt][2] = pack2h(s[2 * kt + 1][0], s[2 * kt + 1][1]);
            Aph[kt][3] = pack2h(s[2 * kt + 1][2], s[2 * kt + 1][3]);
        }

        // ---- O += P V (1-term), V^T in smem [d][j] ----
#pragma unroll
        for (int kt = 0; kt < 4; kt++) {
            u32 Bf[4][4];
            const u32 bkb = (u32)(kt * 32 + ((lane & 8) ? 16 : 0));
#pragma unroll
            for (int bt = 0; bt < 4; bt++) {
                u32 rb = vb + (u32)((bt * 16 + brow) * AROW) + bkb;
                ldsm_x4(rb, Bf[bt]);
            }
#pragma unroll
            for (int nt = 0; nt < 8; nt++)
                mma16816(o[nt], Aph[kt],
                         Bf[nt >> 1][(nt & 1) * 2], Bf[nt >> 1][(nt & 1) * 2 + 1]);
        }
    }

    // ---- epilogue: normalize, store single fp16 ----
    float invA = 1.0f / lA, invB = 1.0f / lB;
    int rowA = b * NTOK + i0 + w * 16 + (lane >> 2);
#pragma unroll
    for (int nt = 0; nt < 8; nt++) {
        int col = h * DH + nt * 8 + 2 * (lane & 3);
        *(u32*)(oh + (size_t)rowA * DIMSZ + col) = pack2h(o[nt][0] * invA, o[nt][1] * invA);
        *(u32*)(oh + (size_t)(rowA + 8) * DIMSZ + col) = pack2h(o[nt][2] * invB, o[nt][3] * invB);
    }
}

// ---------------------------------------------------------------------------
extern "C" void kernel_launch(void* const* d_in, const int* in_sizes, int n_in,
                              void* d_out, int out_size) {
    const float* x    = (const float*)d_in[0];
    const float* rpb  = (const float*)d_in[1];
    const float* Wqkv = (const float*)d_in[2];
    const float* Wout = (const float*)d_in[3];
    const float* bout = (const float*)d_in[4];
    const float* lng  = (const float*)d_in[5];
    const float* lnb  = (const float*)d_in[6];
    float* out = (float*)d_out;

    u16 *xnh, *xnl, *wqh, *woh, *qkh, *qkl, *vth, *ath;
    cudaGetSymbolAddress((void**)&xnh, g_xnh);
    cudaGetSymbolAddress((void**)&xnl, g_xnl);
    cudaGetSymbolAddress((void**)&wqh, g_wqh);
    cudaGetSymbolAddress((void**)&woh, g_woh);
    cudaGetSymbolAddress((void**)&qkh, g_qkvh);
    cudaGetSymbolAddress((void**)&qkl, g_qkvl);
    cudaGetSymbolAddress((void**)&vth, g_vth);
    cudaGetSymbolAddress((void**)&ath, g_atth);

    // 1) LN -> split fp16
    ln_kernel<<<NROWS, 256>>>(x, lng, lnb, xnh, xnl);

    // 1b) weight prep (transpose, single fp16)
    wprep_kernel<<<dim3(QKVN / 32, DIMSZ / 32), 256>>>(Wqkv, wqh, QKVN);
    wprep_kernel<<<dim3(DIMSZ / 32, DIMSZ / 32), 256>>>(Wout, woh, DIMSZ);

    // 2) QKV projection (2-term, split fp16 out, Q pre-scaled)
    cudaFuncSetAttribute(mma_gemm<1, 2>, cudaFuncAttributeMaxDynamicSharedMemorySize, GEMM_SMEM);
    mma_gemm<1, 2><<<dim3(QKVN / 128, NROWS / 128), 512, GEMM_SMEM>>>(
        xnh, xnl, wqh, nullptr, nullptr, qkh, qkl, QKVN);

    // 2b) V transpose
    vtrans_kernel<<<dim3(NTOK / 64, HEADS, BATCH), 256>>>(qkh, vth);

    // 3) attention (QK 2-term, PV 1-term, single fp16 out)
    cudaFuncSetAttribute(attn_mma, cudaFuncAttributeMaxDynamicSharedMemorySize, ASMEM);
    attn_mma<<<dim3(NTOK / 128, HEADS, BATCH), 256, ASMEM>>>(
        qkh, qkl, vth, rpb, ath);

    // 4) output projection (1-term, fp32 out + bias)
    cudaFuncSetAttribute(mma_gemm<0, 1>, cudaFuncAttributeMaxDynamicSharedMemorySize, GEMM_SMEM);
    mma_gemm<0, 1><<<dim3(DIMSZ / 128, NROWS / 128), 512, GEMM_SMEM>>>(
        ath, nullptr, woh, bout, out, nullptr, nullptr, DIMSZ);
}

// round 12
// speedup vs baseline: 2.3186x; 1.3958x over previous
#include <cuda_runtime.h>
#include <cuda_fp16.h>
#include <cstdint>

#define DIMSZ 768
#define NTOK 1024
#define BATCH 8
#define HEADS 12
#define DH 64
#define NROWS (BATCH * NTOK)      /* 8192 */
#define QKVN (3 * DIMSZ)          /* 2304 */
#define SCALE 0.125f              /* DH^-0.5 */

typedef unsigned short u16;
typedef uint32_t u32;

// ---------------- scratch (device globals, allocation-free) ----------------
__device__ u16 g_xnh[NROWS * DIMSZ];     // LN out, fp16
__device__ u16 g_wqh[QKVN * DIMSZ];      // Wqkv^T fp16
__device__ u16 g_woh[DIMSZ * DIMSZ];     // Wout^T fp16
__device__ u16 g_qkvh[NROWS * QKVN];     // qkv fp16
__device__ u16 g_vth[BATCH * HEADS * DH * NTOK];   // V^T fp16
__device__ u16 g_atth[NROWS * DIMSZ];    // attention out fp16

// ---------------- helpers ----------------
__device__ __forceinline__ u32 smem_u32(const void* p) {
    u32 a;
    asm("{ .reg .u64 t; cvta.to.shared.u64 t, %1; cvt.u32.u64 %0, t; }" : "=r"(a) : "l"(p));
    return a;
}
__device__ __forceinline__ void ldsm_x4(u32 addr, u32* r) {
    asm volatile("ldmatrix.sync.aligned.m8n8.x4.shared.b16 {%0,%1,%2,%3}, [%4];"
                 : "=r"(r[0]), "=r"(r[1]), "=r"(r[2]), "=r"(r[3]) : "r"(addr));
}
__device__ __forceinline__ void mma16816(float* c, const u32* a, u32 b0, u32 b1) {
    asm volatile("mma.sync.aligned.m16n8k16.row.col.f32.f16.f16.f32 "
                 "{%0,%1,%2,%3}, {%4,%5,%6,%7}, {%8,%9}, {%0,%1,%2,%3};"
                 : "+f"(c[0]), "+f"(c[1]), "+f"(c[2]), "+f"(c[3])
                 : "r"(a[0]), "r"(a[1]), "r"(a[2]), "r"(a[3]), "r"(b0), "r"(b1));
}
#define CP16(dst, src) \
    asm volatile("cp.async.cg.shared.global [%0], [%1], 16;" :: "r"(dst), "l"(src))
#define CP_COMMIT() asm volatile("cp.async.commit_group;" ::: "memory")
#define CP_WAIT0()  asm volatile("cp.async.wait_group 0;" ::: "memory")
#define CP_WAIT1()  asm volatile("cp.async.wait_group 1;" ::: "memory")

__device__ __forceinline__ u32 pack2h(float a, float b) {
    __half2 v = __floats2half2_rn(a, b);
    return *(u32*)&v;
}

// ===========================================================================
// LayerNorm -> fp16
// ===========================================================================
__global__ __launch_bounds__(256) void ln_kernel(const float* __restrict__ x,
                                                 const float* __restrict__ gamma,
                                                 const float* __restrict__ beta,
                                                 u16* __restrict__ yh) {
    int row = blockIdx.x;
    int t = threadIdx.x;
    __shared__ float sv[DIMSZ];
    __shared__ float sb[8], ssb[8];
    __shared__ float smu, srstd;
    const float* xr = x + (size_t)row * DIMSZ;
    float v0 = xr[t], v1 = xr[t + 256], v2 = xr[t + 512];
    float s = v0 + v1 + v2;
    float ss = v0 * v0 + v1 * v1 + v2 * v2;
#pragma unroll
    for (int o = 16; o > 0; o >>= 1) {
        s += __shfl_xor_sync(0xffffffffu, s, o);
        ss += __shfl_xor_sync(0xffffffffu, ss, o);
    }
    if ((t & 31) == 0) { sb[t >> 5] = s; ssb[t >> 5] = ss; }
    __syncthreads();
    if (t == 0) {
        float S = 0.f, SS = 0.f;
#pragma unroll
        for (int i = 0; i < 8; i++) { S += sb[i]; SS += ssb[i]; }
        float mu = S * (1.0f / DIMSZ);
        float var = SS * (1.0f / DIMSZ) - mu * mu;
        smu = mu;
        srstd = rsqrtf(var + 1e-5f);
    }
    __syncthreads();
    float mu = smu, rstd = srstd;
    sv[t]       = (v0 - mu) * rstd * gamma[t]       + beta[t];
    sv[t + 256] = (v1 - mu) * rstd * gamma[t + 256] + beta[t + 256];
    sv[t + 512] = (v2 - mu) * rstd * gamma[t + 512] + beta[t + 512];
    __syncthreads();
    u32* oh = (u32*)(yh + (size_t)row * DIMSZ);
    for (int p = t; p < DIMSZ / 2; p += 256)
        oh[p] = pack2h(sv[2 * p], sv[2 * p + 1]);
}

// ===========================================================================
// Weight transpose to fp16: W[768][N] -> Wt [N][768]
// ===========================================================================
__global__ __launch_bounds__(256) void wprep_kernel(const float* __restrict__ W,
                                                    u16* __restrict__ Wth,
                                                    int Nsz) {
    __shared__ float sm[32][33];
    int tx = threadIdx.x & 31, ty = threadIdx.x >> 5;   // 32 x 8
    int n0 = blockIdx.x * 32, k0 = blockIdx.y * 32;
#pragma unroll
    for (int i = 0; i < 4; i++)
        sm[ty + i * 8][tx] = W[(size_t)(k0 + ty + i * 8) * Nsz + n0 + tx];
    __syncthreads();
#pragma unroll
    for (int i = 0; i < 4; i++) {
        int n = n0 + ty + i * 8, k = k0 + tx;
        __half hv = __float2half_rn(sm[tx][ty + i * 8]);
        Wth[(size_t)n * DIMSZ + k] = __half_as_ushort(hv);
    }
}

// ===========================================================================
// V transpose: qkv V part [b][j][h*64+d] -> vt [b][h][d][j]
// ===========================================================================
__global__ __launch_bounds__(256) void vtrans_kernel(const u16* __restrict__ qh,
                                                     u16* __restrict__ vh) {
    __shared__ u16 sm[64][66];
    int t = threadIdx.x;
    int j0 = blockIdx.x * 64, h = blockIdx.y, b = blockIdx.z;
#pragma unroll
    for (int i = 0; i < 8; i++) {
        int id = t + i * 256;          // 0..2047
        int jj = id >> 5, dp = id & 31;
        u32 v = *(const u32*)(qh + (size_t)(b * NTOK + j0 + jj) * QKVN +
                              2 * DIMSZ + h * DH + dp * 2);
        sm[jj][2 * dp] = (u16)v;
        sm[jj][2 * dp + 1] = (u16)(v >> 16);
    }
    __syncthreads();
#pragma unroll
    for (int i = 0; i < 8; i++) {
        int id = t + i * 256;
        int d = id >> 5, jp = id & 31;
        u32 v = (u32)sm[2 * jp][d] | ((u32)sm[2 * jp + 1][d] << 16);
        *(u32*)(vh + ((size_t)((b * HEADS + h) * DH + d)) * NTOK + j0 + 2 * jp) = v;
    }
}

// ===========================================================================
// fp16 1-term GEMM: C[M,N] = A[M,768] @ B[N,768]^T (+bias)
// CTA 128x128, 512 thr (16 warps, 32x32 tiles), KC=64, NBUF=3 cp.async.
// EPI 0: fp32 out + bias.  EPI 1: fp16 out, SCALE folded on n<768.
// ===========================================================================
#define TROW 144                  /* 64 fp16 (128B) + 16B pad */
#define TILE (128 * TROW)         /* 18432 */
#define STAGE (2 * TILE)          /* 36864: A, B */
#define NBUF 3
#define GEMM_SMEM (NBUF * STAGE)  /* 110592 */
#define KC 64
#define NSTAGE (DIMSZ / KC)       /* 12 */
#define B_OFF TILE

template <int EPI>
__global__ __launch_bounds__(512, 1) void mma_gemm(const u16* __restrict__ Ah,
                                                   const u16* __restrict__ Bh,
                                                   const float* __restrict__ bias,
                                                   float* __restrict__ Cf,
                                                   u16* __restrict__ Ch,
                                                   int Nsz) {
    extern __shared__ char smem[];
    const u32 smb = smem_u32(smem);
    const int t = threadIdx.x;
    const int wid = t >> 5, lane = t & 31;
    const int m0 = blockIdx.y * 128, n0 = blockIdx.x * 128;
    const int wm = (wid >> 2) * 32, wn = (wid & 3) * 32;

    float acc[2][4][4];
#pragma unroll
    for (int i = 0; i < 2; i++)
#pragma unroll
        for (int j = 0; j < 4; j++)
#pragma unroll
            for (int k = 0; k < 4; k++) acc[i][j][k] = 0.f;

    const int frow = t >> 2;          // 0..127
    const int q4 = t & 3;             // 16-elem quarter

    auto fill = [&](int c) {
        const u32 base = smb + (c % NBUF) * STAGE;
        const size_t aoff = (size_t)(m0 + frow) * DIMSZ + c * KC + q4 * 16;
        const size_t boff = (size_t)(n0 + frow) * DIMSZ + c * KC + q4 * 16;
        const u32 doff = (u32)(frow * TROW + q4 * 32);
        CP16(base + doff, Ah + aoff);
        CP16(base + doff + 16, Ah + aoff + 8);
        CP16(base + B_OFF + doff, Bh + boff);
        CP16(base + B_OFF + doff + 16, Bh + boff + 8);
    };

    const int brow = ((lane >> 4) << 3) + (lane & 7);

    auto compute = [&](int c) {
        const u32 base = smb + (c % NBUF) * STAGE;
#pragma unroll
        for (int ks = 0; ks < 4; ks++) {
            u32 Ahf[2][4], Bhf[2][4];
            const u32 akb = (u32)(ks * 32 + ((lane & 16) ? 16 : 0));
#pragma unroll
            for (int mt = 0; mt < 2; mt++) {
                u32 ra = base + (u32)((wm + mt * 16 + (lane & 15)) * TROW) + akb;
                ldsm_x4(ra, Ahf[mt]);
            }
            const u32 bkb = (u32)(ks * 32 + ((lane & 8) ? 16 : 0));
#pragma unroll
            for (int bt = 0; bt < 2; bt++) {
                u32 rb = base + B_OFF + (u32)((wn + bt * 16 + brow) * TROW) + bkb;
                ldsm_x4(rb, Bhf[bt]);
            }
#pragma unroll
            for (int mt = 0; mt < 2; mt++)
#pragma unroll
                for (int nt = 0; nt < 4; nt++)
                    mma16816(acc[mt][nt], Ahf[mt],
                             Bhf[nt >> 1][(nt & 1) * 2], Bhf[nt >> 1][(nt & 1) * 2 + 1]);
        }
    };

    fill(0); CP_COMMIT();
    fill(1); CP_COMMIT();
    for (int c = 0; c < NSTAGE; c++) {
        CP_WAIT1();
        __syncthreads();
        if (c + 2 < NSTAGE) fill(c + 2);
        CP_COMMIT();
        compute(c);
    }

    // epilogue
#pragma unroll
    for (int mt = 0; mt < 2; mt++) {
        int m = m0 + wm + mt * 16 + (lane >> 2);
#pragma unroll
        for (int nt = 0; nt < 4; nt++) {
            int n = n0 + wn + nt * 8 + (lane & 3) * 2;
            if (EPI == 0) {
                float bx = bias[n], by = bias[n + 1];
                *(float2*)&Cf[(size_t)m * Nsz + n] =
                    make_float2(acc[mt][nt][0] + bx, acc[mt][nt][1] + by);
                *(float2*)&Cf[(size_t)(m + 8) * Nsz + n] =
                    make_float2(acc[mt][nt][2] + bx, acc[mt][nt][3] + by);
            } else {
                float sc = (n < DIMSZ) ? SCALE : 1.0f;
                *(u32*)(Ch + (size_t)m * Nsz + n) =
                    pack2h(acc[mt][nt][0] * sc, acc[mt][nt][1] * sc);
                *(u32*)(Ch + (size_t)(m + 8) * Nsz + n) =
                    pack2h(acc[mt][nt][2] * sc, acc[mt][nt][3] * sc);
            }
        }
    }
}

// ===========================================================================
// Attention, all 1-term fp16: S = Q K^T,  O = P V.
// Block = 256 thr (8 warps), one (b,h,128-q-row tile). K/V cp.async double-buf.
// ===========================================================================
#define AROW 144
#define QTILE (128 * AROW)          /* 18432 (hi only) */
#define KTILE (64 * AROW)           /* 9216 */
#define AKVB (2 * KTILE)            /* Kh,Vh = 18432 */
#define ASMEM (QTILE + 2 * AKVB)    /* 55296; x2 CTAs = 110592 */

__global__ __launch_bounds__(256, 2) void attn_mma(const u16* __restrict__ qh,
                                                   const u16* __restrict__ vth,
                                                   const float* __restrict__ rpb,
                                                   u16* __restrict__ oh) {
    extern __shared__ char smem[];
    const u32 smb = smem_u32(smem);
    const int t = threadIdx.x;
    const int w = t >> 5, lane = t & 31;
    const int i0 = blockIdx.x * 128, h = blockIdx.y, b = blockIdx.z;

    const int brow = ((lane >> 4) << 3) + (lane & 7);

    // ---- Q tile (128 rows) -> smem ----
    {
        const int frow = t >> 1, half = t & 1;
        const size_t qoff = (size_t)(b * NTOK + i0 + frow) * QKVN + h * DH + half * 32;
        const u32 doff = (u32)(frow * AROW + half * 64);
#pragma unroll
        for (int i = 0; i < 4; i++)
            CP16(smb + doff + i * 16, qh + qoff + i * 8);
        CP_COMMIT();
    }

    auto fillKV = [&](int jt) {
        const u32 base = smb + QTILE + (jt & 1) * AKVB;
        const int row = t >> 2, q4 = t & 3;
        const size_t koff = (size_t)(b * NTOK + jt * 64 + row) * QKVN + DIMSZ + h * DH + q4 * 16;
        const size_t voff = (size_t)((b * HEADS + h) * DH + row) * NTOK + jt * 64 + q4 * 16;
        const u32 doff = (u32)(row * AROW + q4 * 32);
        CP16(base + doff, qh + koff);
        CP16(base + doff + 16, qh + koff + 8);
        CP16(base + KTILE + doff, vth + voff);
        CP16(base + KTILE + doff + 16, vth + voff + 8);
    };

    fillKV(0); CP_COMMIT();

    CP_WAIT1();
    __syncthreads();
    u32 Aqh[4][4];
#pragma unroll
    for (int ks = 0; ks < 4; ks++) {
        u32 ra = smb + (u32)((w * 16 + (lane & 15)) * AROW) + ks * 32 + ((lane & 16) ? 16 : 0);
        ldsm_x4(ra, Aqh[ks]);
    }

    float o[8][4];
#pragma unroll
    for (int nt = 0; nt < 8; nt++)
#pragma unroll
        for (int k = 0; k < 4; k++) o[nt][k] = 0.f;
    float mA = -1e30f, mB = -1e30f, lA = 0.f, lB = 0.f;

    const float* bp = rpb + ((size_t)(h * NTOK + i0 + w * 16 + (lane >> 2))) * NTOK + 2 * (lane & 3);

    for (int jt = 0; jt < 16; jt++) {
        CP_WAIT0();
        __syncthreads();
        if (jt + 1 < 16) { fillKV(jt + 1); CP_COMMIT(); }

        const u32 kb = smb + QTILE + (jt & 1) * AKVB;
        const u32 vb = kb + KTILE;

        // ---- S = Q K^T (1-term) ----
        float s[8][4];
#pragma unroll
        for (int nt = 0; nt < 8; nt++)
#pragma unroll
            for (int k = 0; k < 4; k++) s[nt][k] = 0.f;
#pragma unroll
        for (int ks = 0; ks < 4; ks++) {
            u32 Bf[4][4];
            const u32 bkb = (u32)(ks * 32 + ((lane & 8) ? 16 : 0));
#pragma unroll
            for (int bt = 0; bt < 4; bt++) {
                u32 rb = kb + (u32)((bt * 16 + brow) * AROW) + bkb;
                ldsm_x4(rb, Bf[bt]);
            }
#pragma unroll
            for (int nt = 0; nt < 8; nt++)
                mma16816(s[nt], Aqh[ks],
                         Bf[nt >> 1][(nt & 1) * 2], Bf[nt >> 1][(nt & 1) * 2 + 1]);
        }

        // ---- + bias, online softmax ----
        const float* bpj = bp + jt * 64;
        float tmA = -1e30f, tmB = -1e30f;
#pragma unroll
        for (int nt = 0; nt < 8; nt++) {
            float2 ba = *(const float2*)(bpj + nt * 8);
            float2 bb = *(const float2*)(bpj + 8 * NTOK + nt * 8);
            s[nt][0] += ba.x; s[nt][1] += ba.y;
            s[nt][2] += bb.x; s[nt][3] += bb.y;
            tmA = fmaxf(tmA, fmaxf(s[nt][0], s[nt][1]));
            tmB = fmaxf(tmB, fmaxf(s[nt][2], s[nt][3]));
        }
        tmA = fmaxf(tmA, __shfl_xor_sync(0xffffffffu, tmA, 1));
        tmA = fmaxf(tmA, __shfl_xor_sync(0xffffffffu, tmA, 2));
        tmB = fmaxf(tmB, __shfl_xor_sync(0xffffffffu, tmB, 1));
        tmB = fmaxf(tmB, __shfl_xor_sync(0xffffffffu, tmB, 2));
        float nmA = fmaxf(mA, tmA), nmB = fmaxf(mB, tmB);
        float facA = __expf(mA - nmA), facB = __expf(mB - nmB);
        mA = nmA; mB = nmB;
        float suA = 0.f, suB = 0.f;
#pragma unroll
        for (int nt = 0; nt < 8; nt++) {
            s[nt][0] = __expf(s[nt][0] - mA);
            s[nt][1] = __expf(s[nt][1] - mA);
            s[nt][2] = __expf(s[nt][2] - mB);
            s[nt][3] = __expf(s[nt][3] - mB);
            suA += s[nt][0] + s[nt][1];
            suB += s[nt][2] + s[nt][3];
            o[nt][0] *= facA; o[nt][1] *= facA;
            o[nt][2] *= facB; o[nt][3] *= facB;
        }
        suA += __shfl_xor_sync(0xffffffffu, suA, 1);
        suA += __shfl_xor_sync(0xffffffffu, suA, 2);
        suB += __shfl_xor_sync(0xffffffffu, suB, 1);
        suB += __shfl_xor_sync(0xffffffffu, suB, 2);
        lA = lA * facA + suA;
        lB = lB * facB + suB;

        // ---- P fragments (fp16) ----
        u32 Aph[4][4];
#pragma unroll
        for (int kt = 0; kt < 4; kt++) {
            Aph[kt][0] = pack2h(s[2 * kt][0], s[2 * kt][1]);
            Aph[kt][1] = pack2h(s[2 * kt][2], s[2 * kt][3]);
            Aph[kt][2] = pack2h(s[2 * kt + 1][0], s[2 * kt + 1][1]);
            Aph[kt][3] = pack2h(s[2 * kt + 1][2], s[2 * kt + 1][3]);
        }

        // ---- O += P V (1-term), V^T in smem [d][j] ----
#pragma unroll
        for (int kt = 0; kt < 4; kt++) {
            u32 Bf[4][4];
            const u32 bkb = (u32)(kt * 32 + ((lane & 8) ? 16 : 0));
#pragma unroll
            for (int bt = 0; bt < 4; bt++) {
                u32 rb = vb + (u32)((bt * 16 + brow) * AROW) + bkb;
                ldsm_x4(rb, Bf[bt]);
            }
#pragma unroll
            for (int nt = 0; nt < 8; nt++)
                mma16816(o[nt], Aph[kt],
                         Bf[nt >> 1][(nt & 1) * 2], Bf[nt >> 1][(nt & 1) * 2 + 1]);
        }
    }

    // ---- epilogue: normalize, store fp16 ----
    float invA = 1.0f / lA, invB = 1.0f / lB;
    int rowA = b * NTOK + i0 + w * 16 + (lane >> 2);
#pragma unroll
    for (int nt = 0; nt < 8; nt++) {
        int col = h * DH + nt * 8 + 2 * (lane & 3);
        *(u32*)(oh + (size_t)rowA * DIMSZ + col) = pack2h(o[nt][0] * invA, o[nt][1] * invA);
        *(u32*)(oh + (size_t)(rowA + 8) * DIMSZ + col) = pack2h(o[nt][2] * invB, o[nt][3] * invB);
    }
}

// ---------------------------------------------------------------------------
extern "C" void kernel_launch(void* const* d_in, const int* in_sizes, int n_in,
                              void* d_out, int out_size) {
    const float* x    = (const float*)d_in[0];
    const float* rpb  = (const float*)d_in[1];
    const float* Wqkv = (const float*)d_in[2];
    const float* Wout = (const float*)d_in[3];
    const float* bout = (const float*)d_in[4];
    const float* lng  = (const float*)d_in[5];
    const float* lnb  = (const float*)d_in[6];
    float* out = (float*)d_out;

    u16 *xnh, *wqh, *woh, *qkh, *vth, *ath;
    cudaGetSymbolAddress((void**)&xnh, g_xnh);
    cudaGetSymbolAddress((void**)&wqh, g_wqh);
    cudaGetSymbolAddress((void**)&woh, g_woh);
    cudaGetSymbolAddress((void**)&qkh, g_qkvh);
    cudaGetSymbolAddress((void**)&vth, g_vth);
    cudaGetSymbolAddress((void**)&ath, g_atth);

    // 1) LN -> fp16
    ln_kernel<<<NROWS, 256>>>(x, lng, lnb, xnh);

    // 1b) weight prep (transpose, fp16)
    wprep_kernel<<<dim3(QKVN / 32, DIMSZ / 32), 256>>>(Wqkv, wqh, QKVN);
    wprep_kernel<<<dim3(DIMSZ / 32, DIMSZ / 32), 256>>>(Wout, woh, DIMSZ);

    // 2) QKV projection (1-term, fp16 out, Q pre-scaled)
    cudaFuncSetAttribute(mma_gemm<1>, cudaFuncAttributeMaxDynamicSharedMemorySize, GEMM_SMEM);
    mma_gemm<1><<<dim3(QKVN / 128, NROWS / 128), 512, GEMM_SMEM>>>(
        xnh, wqh, nullptr, nullptr, qkh, QKVN);

    // 2b) V transpose
    vtrans_kernel<<<dim3(NTOK / 64, HEADS, BATCH), 256>>>(qkh, vth);

    // 3) attention (all 1-term fp16)
    cudaFuncSetAttribute(attn_mma, cudaFuncAttributeMaxDynamicSharedMemorySize, ASMEM);
    attn_mma<<<dim3(NTOK / 128, HEADS, BATCH), 256, ASMEM>>>(
        qkh, vth, rpb, ath);

    // 4) output projection (1-term, fp32 out + bias)
    cudaFuncSetAttribute(mma_gemm<0>, cudaFuncAttributeMaxDynamicSharedMemorySize, GEMM_SMEM);
    mma_gemm<0><<<dim3(DIMSZ / 128, NROWS / 128), 512, GEMM_SMEM>>>(
        ath, woh, bout, out, nullptr, DIMSZ);
}